// round 12
// baseline (speedup 1.0000x reference)
#include <cuda_runtime.h>
#include <cuda_fp16.h>
#include <cstdint>

#define C_DIM 256
#define L_DIM 1024
#define B_DIM 16
#define NH 8
#define DH 32
#define SCALE 0.17677669529663687f
#define LOG2E 1.4426950408889634f

// f16 hi/lo split buffers
__device__ __half g_qh[B_DIM * L_DIM * C_DIM];   // [b][l][c]
__device__ __half g_kth[B_DIM * L_DIM * C_DIM];  // k [b][l][c]
__device__ __half g_ktl[B_DIM * L_DIM * C_DIM];
__device__ __half g_vth[B_DIM * L_DIM * C_DIM];  // v [b][l][c]
__device__ __half g_vtl[B_DIM * L_DIM * C_DIM];
__device__ __half g_xth[B_DIM * L_DIM * C_DIM];  // x^T split; reused as att split [b][c][l]
__device__ __half g_xtl[B_DIM * L_DIM * C_DIM];
__device__ __half g_wh[3 * C_DIM * C_DIM];       // W^T [sel][c][o]
__device__ __half g_wl[3 * C_DIM * C_DIM];
__device__ __half g_woh[C_DIM * C_DIM];          // Wo [o][c]
__device__ __half g_wol[C_DIM * C_DIM];

__device__ __forceinline__ float ex2f(float x) {
    float r; asm("ex2.approx.f32 %0, %1;" : "=f"(r) : "f"(x)); return r;
}
__device__ __forceinline__ uint32_t smem_u32(const void* p) {
    uint32_t a;
    asm("{ .reg .u64 t; cvta.to.shared.u64 t, %1; cvt.u32.u64 %0, t; }" : "=r"(a) : "l"(p));
    return a;
}
__device__ __forceinline__ uint32_t pack_h2(float lo, float hi) {
    uint32_t r; asm("cvt.rn.f16x2.f32 %0, %1, %2;" : "=r"(r) : "f"(hi), "f"(lo)); return r;
}
__device__ __forceinline__ void ldsm_x4(uint32_t* r, uint32_t a) {
    asm volatile("ldmatrix.sync.aligned.m8n8.x4.shared.b16 {%0,%1,%2,%3}, [%4];"
        : "=r"(r[0]), "=r"(r[1]), "=r"(r[2]), "=r"(r[3]) : "r"(a));
}
__device__ __forceinline__ void ldsm_x4t(uint32_t* r, uint32_t a) {
    asm volatile("ldmatrix.sync.aligned.m8n8.x4.trans.shared.b16 {%0,%1,%2,%3}, [%4];"
        : "=r"(r[0]), "=r"(r[1]), "=r"(r[2]), "=r"(r[3]) : "r"(a));
}
__device__ __forceinline__ void mma16816(float* d, const uint32_t* a, const uint32_t* b) {
    asm volatile("mma.sync.aligned.m16n8k16.row.col.f32.f16.f16.f32 "
        "{%0,%1,%2,%3}, {%4,%5,%6,%7}, {%8,%9}, {%0,%1,%2,%3};"
        : "+f"(d[0]), "+f"(d[1]), "+f"(d[2]), "+f"(d[3])
        : "r"(a[0]), "r"(a[1]), "r"(a[2]), "r"(a[3]), "r"(b[0]), "r"(b[1]));
}
__device__ __forceinline__ float shflx(float v, int m) {
    return __shfl_xor_sync(0xffffffffu, v, m);
}
__device__ __forceinline__ void cpa16(uint32_t s, const void* g) {
    asm volatile("cp.async.cg.shared.global [%0], [%1], 16;" :: "r"(s), "l"(g));
}
#define CP_COMMIT() asm volatile("cp.async.commit_group;" ::: "memory")
#define CP_WAIT0()  asm volatile("cp.async.wait_group 0;" ::: "memory")

// ------------------- prep kernels (unchanged) -------------------
__global__ void __launch_bounds__(256)
split_w_kernel(const float* __restrict__ wq, const float* __restrict__ wk, const float* __restrict__ wv)
{
    __shared__ float t[32][33];
    const int sel = blockIdx.z;
    const float* W = (sel == 0) ? wq : (sel == 1) ? wk : wv;
    __half* dh = g_wh + sel * C_DIM * C_DIM;
    __half* dl = g_wl + sel * C_DIM * C_DIM;
    const int o0 = blockIdx.x * 32, c0 = blockIdx.y * 32;
    const int tx = threadIdx.x, ty = threadIdx.y;
    #pragma unroll
    for (int i = 0; i < 4; i++)
        t[ty + 8 * i][tx] = W[(o0 + ty + 8 * i) * C_DIM + c0 + tx];
    __syncthreads();
    #pragma unroll
    for (int i = 0; i < 4; i++) {
        float v = t[tx][ty + 8 * i];
        __half h = __float2half_rn(v);
        int o = (c0 + ty + 8 * i) * C_DIM + o0 + tx;
        dh[o] = h;
        dl[o] = __float2half_rn(v - __half2float(h));
    }
}

__global__ void __launch_bounds__(256)
split_wo_kernel(const float* __restrict__ wo)
{
    int i = blockIdx.x * 256 + threadIdx.x;
    const float2 v = ((const float2*)wo)[i];
    __half2 h = __floats2half2_rn(v.x, v.y);
    float2 hf = __half22float2(h);
    ((__half2*)g_woh)[i] = h;
    ((__half2*)g_wol)[i] = __floats2half2_rn(v.x - hf.x, v.y - hf.y);
}

__global__ void __launch_bounds__(256)
convert_x_kernel(const float* __restrict__ x)
{
    __shared__ float t[32][33];
    const int b = blockIdx.z;
    const float* src = x + (size_t)b * C_DIM * L_DIM;
    __half* dh = g_xth + (size_t)b * L_DIM * C_DIM;
    __half* dl = g_xtl + (size_t)b * L_DIM * C_DIM;
    const int l0 = blockIdx.x * 32, c0 = blockIdx.y * 32;
    const int tx = threadIdx.x, ty = threadIdx.y;
    #pragma unroll
    for (int i = 0; i < 4; i++)
        t[ty + 8 * i][tx] = src[(size_t)(c0 + ty + 8 * i) * L_DIM + l0 + tx];
    __syncthreads();
    #pragma unroll
    for (int i = 0; i < 4; i++) {
        float v = t[tx][ty + 8 * i];
        __half h = __float2half_rn(v);
        size_t o = (size_t)(l0 + ty + 8 * i) * C_DIM + c0 + tx;
        dh[o] = h;
        dl[o] = __float2half_rn(v - __half2float(h));
    }
}

// ------------------- mma QKV projection: 64x128 tiles, 3 CTAs/SM -------------------
// dyn smem stage (halves): AH 0 (2560), AL 2560, BH 5120 (4352), BL 9472; stage = 13824
#define PJ_STAGE 13824
#define PJ_BYTES (2 * PJ_STAGE * 2)

__global__ void __launch_bounds__(256, 3)
proj_qkv_mma_kernel(const float* __restrict__ bq, const float* __restrict__ bk,
                    const float* __restrict__ bv)
{
    extern __shared__ __half dynsm[];
    __shared__ float bias_s[128];

    const int tid = threadIdx.x, lane = tid & 31, w = tid >> 5;
    const int lt = blockIdx.x >> 1, oh = blockIdx.x & 1;   // lt: 0..15 (64 l-rows each)
    const int sel = blockIdx.y, b = blockIdx.z;
    const int wr = w & 3;        // row group (16 rows)
    const int wc = w >> 2;       // col half (64 cols)

    const __half* xh = g_xth + (size_t)b * L_DIM * C_DIM;
    const __half* xl = g_xtl + (size_t)b * L_DIM * C_DIM;
    const __half* wh = g_wh + sel * C_DIM * C_DIM;
    const __half* wl = g_wl + sel * C_DIM * C_DIM;
    const float* bias = (sel == 0) ? bq : (sel == 1) ? bk : bv;
    __half* Yh = (sel == 0) ? g_qh : (sel == 1) ? g_kth : g_vth;
    __half* Yl = (sel == 0) ? (__half*)0 : (sel == 1) ? g_ktl : g_vtl;
    const float sc = (sel == 0) ? (SCALE * LOG2E) : 1.0f;

    if (tid < 128) bias_s[tid] = bias[oh * 128 + tid];

    const int arow = tid >> 2, aseg = tid & 3;       // A: 64 rows x 4 segs
    const int brow = tid >> 4, bseg = tid & 15;      // B: 16 rows/pass x 16 segs

    {
        __half* base = dynsm;
        size_t ga = (size_t)(lt * 64 + arow) * C_DIM + aseg * 8;
        cpa16(smem_u32(base + arow * 40 + aseg * 8), &xh[ga]);
        cpa16(smem_u32(base + 2560 + arow * 40 + aseg * 8), &xl[ga]);
        #pragma unroll
        for (int i = 0; i < 2; i++) {
            int row = brow + i * 16;
            int g = row * C_DIM + oh * 128 + bseg * 8;
            cpa16(smem_u32(base + 5120 + row * 136 + bseg * 8), &wh[g]);
            cpa16(smem_u32(base + 9472 + row * 136 + bseg * 8), &wl[g]);
        }
        CP_COMMIT();
    }

    float acc[8][4] = {};
    const int rr = lane & 15;
    const int chi = (lane & 16) ? 8 : 0;

    for (int it = 0; it < 8; it++) {
        CP_WAIT0();
        __syncthreads();

        if (it < 7) {
            __half* base = dynsm + ((it + 1) & 1) * PJ_STAGE;
            int kc0 = (it + 1) * 32;
            size_t ga = (size_t)(lt * 64 + arow) * C_DIM + kc0 + aseg * 8;
            cpa16(smem_u32(base + arow * 40 + aseg * 8), &xh[ga]);
            cpa16(smem_u32(base + 2560 + arow * 40 + aseg * 8), &xl[ga]);
            #pragma unroll
            for (int i = 0; i < 2; i++) {
                int row = brow + i * 16;
                int g = (kc0 + row) * C_DIM + oh * 128 + bseg * 8;
                cpa16(smem_u32(base + 5120 + row * 136 + bseg * 8), &wh[g]);
                cpa16(smem_u32(base + 9472 + row * 136 + bseg * 8), &wl[g]);
            }
            CP_COMMIT();
        }

        __half* cur = dynsm + (it & 1) * PJ_STAGE;
        __half* ah = cur;
        __half* al = cur + 2560;
        __half* bh_s = cur + 5120;
        __half* bl_s = cur + 9472;

        uint32_t af[2][2][4];
        #pragma unroll
        for (int kc = 0; kc < 2; kc++) {
            ldsm_x4(af[0][kc], smem_u32(&ah[(wr * 16 + rr) * 40 + kc * 16 + chi]));
            ldsm_x4(af[1][kc], smem_u32(&al[(wr * 16 + rr) * 40 + kc * 16 + chi]));
        }

        #pragma unroll
        for (int nt = 0; nt < 8; nt += 2) {
            #pragma unroll
            for (int kc = 0; kc < 2; kc++) {
                uint32_t bh[4], bl[4];
                uint32_t off = (kc * 16 + rr) * 136 + wc * 64 + nt * 8 + chi;
                ldsm_x4t(bh, smem_u32(&bh_s[off]));
                ldsm_x4t(bl, smem_u32(&bl_s[off]));
                mma16816(acc[nt],     af[0][kc], bh);
                mma16816(acc[nt + 1], af[0][kc], bh + 2);
                mma16816(acc[nt],     af[0][kc], bl);
                mma16816(acc[nt + 1], af[0][kc], bl + 2);
                mma16816(acc[nt],     af[1][kc], bh);
                mma16816(acc[nt + 1], af[1][kc], bh + 2);
            }
        }
    }

    // epilogue: write f16 hi (and lo, except for q) in [b][l][c]
    const int r0 = lt * 64 + wr * 16 + (lane >> 2);
    #pragma unroll
    for (int nt = 0; nt < 8; nt++) {
        int c0 = wc * 64 + nt * 8 + (lane & 3) * 2;
        float b0 = bias_s[c0], b1 = bias_s[c0 + 1];
        float v0 = (acc[nt][0] + b0) * sc, v1 = (acc[nt][1] + b1) * sc;
        float v2 = (acc[nt][2] + b0) * sc, v3 = (acc[nt][3] + b1) * sc;
        __half2 h0 = __floats2half2_rn(v0, v1);
        __half2 h1 = __floats2half2_rn(v2, v3);
        size_t o0 = (size_t)(b * 1024 + r0) * C_DIM + oh * 128 + c0;
        size_t o1 = (size_t)(b * 1024 + r0 + 8) * C_DIM + oh * 128 + c0;
        *(__half2*)&Yh[o0] = h0;
        *(__half2*)&Yh[o1] = h1;
        if (sel != 0) {
            float2 f0 = __half22float2(h0);
            float2 f1 = __half22float2(h1);
            *(__half2*)&Yl[o0] = __floats2half2_rn(v0 - f0.x, v1 - f0.y);
            *(__half2*)&Yl[o1] = __floats2half2_rn(v2 - f1.x, v3 - f1.y);
        }
    }
}

// ------------------- flash attention (byte-identical to R11 win) -------------------
__global__ void __launch_bounds__(256, 2)
attn_mma_kernel()
{
    __shared__ __align__(16) __half pool[20480];

    const int tid = threadIdx.x, lane = tid & 31, w = tid >> 5;
    const int qt = blockIdx.x, n = blockIdx.y, b = blockIdx.z;
    const int rr = lane & 15;
    const int hoff = (lane & 16) ? 8 : 0;
    const int knr = (lane & 7) + ((lane >> 4) << 3);
    const int knc = ((lane >> 3) & 1) * 8;
    const int kvrow = tid >> 2, kvseg = tid & 3;

    {
        __half* base = pool + 10240;
        size_t g = ((size_t)(b * 1024 + kvrow)) * C_DIM + n * 32 + kvseg * 8;
        uint32_t s = smem_u32(base + kvrow * 40 + kvseg * 8);
        cpa16(s, &g_kth[g]);
        cpa16(s + 2560 * 2, &g_ktl[g]);
        cpa16(s + 5120 * 2, &g_vth[g]);
        cpa16(s + 7680 * 2, &g_vtl[g]);
        CP_COMMIT();
    }

    for (int u = tid; u < 512; u += 256) {
        int row = u >> 2, seg = u & 3;
        size_t g = ((size_t)(b * 1024 + qt * 128 + row)) * C_DIM + n * 32 + seg * 8;
        *(uint4*)&pool[row * 40 + seg * 8] = *(const uint4*)&g_qh[g];
    }
    __syncthreads();

    uint32_t qf[2][4];
    #pragma unroll
    for (int kc = 0; kc < 2; kc++)
        ldsm_x4(qf[kc], smem_u32(&pool[(w * 16 + rr) * 40 + kc * 16 + hoff]));
    __syncthreads();

    float oacc[4][4] = {};
    float m0 = -1e30f, m1 = -1e30f, l0 = 0.0f, l1 = 0.0f;

    for (int t = 0; t < 16; t++) {
        CP_WAIT0();
        __syncthreads();

        if (t < 15) {
            __half* base = pool + (((t + 1) & 1) ? 0 : 10240);
            size_t g = ((size_t)(b * 1024 + (t + 1) * 64 + kvrow)) * C_DIM + n * 32 + kvseg * 8;
            uint32_t s = smem_u32(base + kvrow * 40 + kvseg * 8);
            cpa16(s, &g_kth[g]);
            cpa16(s + 2560 * 2, &g_ktl[g]);
            cpa16(s + 5120 * 2, &g_vth[g]);
            cpa16(s + 7680 * 2, &g_vtl[g]);
            CP_COMMIT();
        }

        __half* cur = pool + ((t & 1) ? 0 : 10240);
        __half* ksh0 = cur;
        __half* ksh1 = cur + 2560;
        __half* vsh0 = cur + 5120;
        __half* vsh1 = cur + 7680;

        float sacc[8][4];
        #pragma unroll
        for (int ntp = 0; ntp < 4; ntp++) {
            float* s0 = sacc[2 * ntp];
            float* s1 = sacc[2 * ntp + 1];
            s0[0] = s0[1] = s0[2] = s0[3] = 0.0f;
            s1[0] = s1[1] = s1[2] = s1[3] = 0.0f;
            #pragma unroll
            for (int kc = 0; kc < 2; kc++) {
                uint32_t off = (ntp * 16 + knr) * 40 + kc * 16 + knc;
                uint32_t kbh[4], kbl[4];
                ldsm_x4(kbh, smem_u32(&ksh0[off]));
                ldsm_x4(kbl, smem_u32(&ksh1[off]));
                mma16816(s0, qf[kc], kbh);
                mma16816(s1, qf[kc], kbh + 2);
                mma16816(s0, qf[kc], kbl);
                mma16816(s1, qf[kc], kbl + 2);
            }
        }

        float mt0 = -1e30f, mt1 = -1e30f;
        #pragma unroll
        for (int nt = 0; nt < 8; nt++) {
            mt0 = fmaxf(mt0, fmaxf(sacc[nt][0], sacc[nt][1]));
            mt1 = fmaxf(mt1, fmaxf(sacc[nt][2], sacc[nt][3]));
        }
        mt0 = fmaxf(mt0, shflx(mt0, 1)); mt0 = fmaxf(mt0, shflx(mt0, 2));
        mt1 = fmaxf(mt1, shflx(mt1, 1)); mt1 = fmaxf(mt1, shflx(mt1, 2));
        float nm0 = fmaxf(m0, mt0), nm1 = fmaxf(m1, mt1);
        float c0 = ex2f(m0 - nm0), c1 = ex2f(m1 - nm1);
        m0 = nm0; m1 = nm1;
        l0 *= c0; l1 *= c1;
        #pragma unroll
        for (int nt = 0; nt < 4; nt++) {
            oacc[nt][0] *= c0; oacc[nt][1] *= c0;
            oacc[nt][2] *= c1; oacc[nt][3] *= c1;
        }
        float rs0 = 0.0f, rs1 = 0.0f;
        #pragma unroll
        for (int nt = 0; nt < 8; nt++) {
            sacc[nt][0] = ex2f(sacc[nt][0] - m0);
            sacc[nt][1] = ex2f(sacc[nt][1] - m0);
            sacc[nt][2] = ex2f(sacc[nt][2] - m1);
            sacc[nt][3] = ex2f(sacc[nt][3] - m1);
            rs0 += sacc[nt][0] + sacc[nt][1];
            rs1 += sacc[nt][2] + sacc[nt][3];
        }
        rs0 += shflx(rs0, 1); rs0 += shflx(rs0, 2);
        rs1 += shflx(rs1, 1); rs1 += shflx(rs1, 2);
        l0 += rs0; l1 += rs1;

        uint32_t pfh[4][4];
        #pragma unroll
        for (int kc = 0; kc < 4; kc++) {
            const float* s0 = sacc[2 * kc];
            const float* s1 = sacc[2 * kc + 1];
            pfh[kc][0] = pack_h2(s0[0], s0[1]);
            pfh[kc][1] = pack_h2(s0[2], s0[3]);
            pfh[kc][2] = pack_h2(s1[0], s1[1]);
            pfh[kc][3] = pack_h2(s1[2], s1[3]);
        }

        #pragma unroll
        for (int kc = 0; kc < 4; kc++) {
            #pragma unroll
            for (int np = 0; np < 2; np++) {
                uint32_t vbh[4], vbl[4];
                uint32_t off = (kc * 16 + rr) * 40 + np * 16 + hoff;
                ldsm_x4t(vbh, smem_u32(&vsh0[off]));
                ldsm_x4t(vbl, smem_u32(&vsh1[off]));
                mma16816(oacc[2 * np],     pfh[kc], vbh);
                mma16816(oacc[2 * np + 1], pfh[kc], vbh + 2);
                mma16816(oacc[2 * np],     pfh[kc], vbl);
                mma16816(oacc[2 * np + 1], pfh[kc], vbl + 2);
            }
        }
    }

    float i0 = 1.0f / l0, i1 = 1.0f / l1;
    int q0 = qt * 128 + w * 16 + (lane >> 2);
    #pragma unroll
    for (int nt = 0; nt < 4; nt++) {
        int c = n * 32 + nt * 8 + (lane & 3) * 2;
        float v00 = oacc[nt][0] * i0, v01 = oacc[nt][1] * i0;
        float v10 = oacc[nt][2] * i1, v11 = oacc[nt][3] * i1;
        size_t b0 = ((size_t)(b * 256 + c)) * L_DIM + q0;
        size_t b1 = b0 + L_DIM;
        __half h;
        h = __float2half_rn(v00); g_xth[b0] = h;     g_xtl[b0] = __float2half_rn(v00 - __half2float(h));
        h = __float2half_rn(v01); g_xth[b1] = h;     g_xtl[b1] = __float2half_rn(v01 - __half2float(h));
        h = __float2half_rn(v10); g_xth[b0 + 8] = h; g_xtl[b0 + 8] = __float2half_rn(v10 - __half2float(h));
        h = __float2half_rn(v11); g_xth[b1 + 8] = h; g_xtl[b1 + 8] = __float2half_rn(v11 - __half2float(h));
    }
}

// ------------------- mma output projection: 64x128 tiles, 3 CTAs/SM -------------------
__global__ void __launch_bounds__(256, 3)
proj_o_mma_kernel(const float* __restrict__ bo, float* __restrict__ out)
{
    extern __shared__ __half dynsm[];
    __shared__ float bias_s[64];

    const int tid = threadIdx.x, lane = tid & 31, w = tid >> 5;
    const int ot = blockIdx.x >> 3, ltile = blockIdx.x & 7;   // ot: 0..3 (64 o-rows), ltile: 0..7
    const int b = blockIdx.z;
    const int wr = w & 3;
    const int wc = w >> 2;

    if (tid < 64) bias_s[tid] = bo[ot * 64 + tid];

    const int arow = tid >> 2, aseg = tid & 3;
    const int brow = tid >> 4, bseg = tid & 15;

    {
        __half* base = dynsm;
        int ga = (ot * 64 + arow) * C_DIM + aseg * 8;
        cpa16(smem_u32(base + arow * 40 + aseg * 8), &g_woh[ga]);
        cpa16(smem_u32(base + 2560 + arow * 40 + aseg * 8), &g_wol[ga]);
        #pragma unroll
        for (int i = 0; i < 2; i++) {
            int row = brow + i * 16;
            size_t g = ((size_t)(b * 256 + row)) * L_DIM + ltile * 128 + bseg * 8;
            cpa16(smem_u32(base + 5120 + row * 136 + bseg * 8), &g_xth[g]);
            cpa16(smem_u32(base + 9472 + row * 136 + bseg * 8), &g_xtl[g]);
        }
        CP_COMMIT();
    }

    float acc[8][4] = {};
    const int rr = lane & 15;
    const int chi = (lane & 16) ? 8 : 0;

    for (int it = 0; it < 8; it++) {
        CP_WAIT0();
        __syncthreads();

        if (it < 7) {
            __half* base = dynsm + ((it + 1) & 1) * PJ_STAGE;
            int kc0 = (it + 1) * 32;
            int ga = (ot * 64 + arow) * C_DIM + kc0 + aseg * 8;
            cpa16(smem_u32(base + arow * 40 + aseg * 8), &g_woh[ga]);
            cpa16(smem_u32(base + 2560 + arow * 40 + aseg * 8), &g_wol[ga]);
            #pragma unroll
            for (int i = 0; i < 2; i++) {
                int row = brow + i * 16;
                size_t g = ((size_t)(b * 256 + kc0 + row)) * L_DIM + ltile * 128 + bseg * 8;
                cpa16(smem_u32(base + 5120 + row * 136 + bseg * 8), &g_xth[g]);
                cpa16(smem_u32(base + 9472 + row * 136 + bseg * 8), &g_xtl[g]);
            }
            CP_COMMIT();
        }

        __half* cur = dynsm + (it & 1) * PJ_STAGE;
        __half* ah = cur;
        __half* al = cur + 2560;
        __half* bh_s = cur + 5120;
        __half* bl_s = cur + 9472;

        uint32_t af[2][2][4];
        #pragma unroll
        for (int kc = 0; kc < 2; kc++) {
            ldsm_x4(af[0][kc], smem_u32(&ah[(wr * 16 + rr) * 40 + kc * 16 + chi]));
            ldsm_x4(af[1][kc], smem_u32(&al[(wr * 16 + rr) * 40 + kc * 16 + chi]));
        }

        #pragma unroll
        for (int nt = 0; nt < 8; nt += 2) {
            #pragma unroll
            for (int kc = 0; kc < 2; kc++) {
                uint32_t bh[4], bl[4];
                uint32_t off = (kc * 16 + rr) * 136 + wc * 64 + nt * 8 + chi;
                ldsm_x4t(bh, smem_u32(&bh_s[off]));
                ldsm_x4t(bl, smem_u32(&bl_s[off]));
                mma16816(acc[nt],     af[0][kc], bh);
                mma16816(acc[nt + 1], af[0][kc], bh + 2);
                mma16816(acc[nt],     af[0][kc], bl);
                mma16816(acc[nt + 1], af[0][kc], bl + 2);
                mma16816(acc[nt],     af[1][kc], bh);
                mma16816(acc[nt + 1], af[1][kc], bh + 2);
            }
        }
    }

    const int orow = ot * 64 + wr * 16 + (lane >> 2);
    const float bb0 = bias_s[wr * 16 + (lane >> 2)];
    const float bb1 = bias_s[wr * 16 + (lane >> 2) + 8];
    #pragma unroll
    for (int nt = 0; nt < 8; nt++) {
        int lcol = ltile * 128 + wc * 64 + nt * 8 + (lane & 3) * 2;
        float2 y0, y1;
        y0.x = acc[nt][0] + bb0; y0.y = acc[nt][1] + bb0;
        y1.x = acc[nt][2] + bb1; y1.y = acc[nt][3] + bb1;
        *(float2*)&out[((size_t)(b * 256 + orow)) * L_DIM + lcol] = y0;
        *(float2*)&out[((size_t)(b * 256 + orow + 8)) * L_DIM + lcol] = y1;
    }
}

// ---------------------------------------------------------------------------
extern "C" void kernel_launch(void* const* d_in, const int* in_sizes, int n_in,
                              void* d_out, int out_size)
{
    const float* x  = (const float*)d_in[0];
    const float* wq = (const float*)d_in[1];
    const float* bq = (const float*)d_in[2];
    const float* wk = (const float*)d_in[3];
    const float* bk = (const float*)d_in[4];
    const float* wv = (const float*)d_in[5];
    const float* bv = (const float*)d_in[6];
    const float* wo = (const float*)d_in[7];
    const float* bo = (const float*)d_in[8];
    float* out = (float*)d_out;

    cudaFuncSetAttribute(proj_qkv_mma_kernel, cudaFuncAttributeMaxDynamicSharedMemorySize, PJ_BYTES);
    cudaFuncSetAttribute(proj_o_mma_kernel, cudaFuncAttributeMaxDynamicSharedMemorySize, PJ_BYTES);

    split_w_kernel<<<dim3(8, 8, 3), dim3(32, 8)>>>(wq, wk, wv);
    split_wo_kernel<<<128, 256>>>(wo);
    convert_x_kernel<<<dim3(32, 8, 16), dim3(32, 8)>>>(x);
    proj_qkv_mma_kernel<<<dim3(32, 3, 16), 256, PJ_BYTES>>>(bq, bk, bv);
    attn_mma_kernel<<<dim3(8, 8, 16), 256>>>();
    proj_o_mma_kernel<<<dim3(32, 1, 16), 256, PJ_BYTES>>>(bo, out);
}

// round 13
// speedup vs baseline: 1.0908x; 1.0908x over previous
#include <cuda_runtime.h>
#include <cuda_fp16.h>
#include <cstdint>

#define C_DIM 256
#define L_DIM 1024
#define B_DIM 16
#define NH 8
#define DH 32
#define SCALE 0.17677669529663687f
#define LOG2E 1.4426950408889634f

// f16 hi/lo split buffers
__device__ __half g_qh[B_DIM * L_DIM * C_DIM];   // [b][l][c]
__device__ __half g_kth[B_DIM * L_DIM * C_DIM];  // k [b][l][c]
__device__ __half g_ktl[B_DIM * L_DIM * C_DIM];
__device__ __half g_vth[B_DIM * L_DIM * C_DIM];  // v [b][l][c]
__device__ __half g_vtl[B_DIM * L_DIM * C_DIM];
__device__ __half g_xth[B_DIM * L_DIM * C_DIM];  // x^T split; reused as att split [b][c][l]
__device__ __half g_xtl[B_DIM * L_DIM * C_DIM];
__device__ __half g_wh[3 * C_DIM * C_DIM];       // W^T [sel][c][o]
__device__ __half g_wl[3 * C_DIM * C_DIM];
__device__ __half g_woh[C_DIM * C_DIM];          // Wo [o][c]
__device__ __half g_wol[C_DIM * C_DIM];

__device__ __forceinline__ float ex2f(float x) {
    float r; asm("ex2.approx.f32 %0, %1;" : "=f"(r) : "f"(x)); return r;
}
__device__ __forceinline__ uint32_t smem_u32(const void* p) {
    uint32_t a;
    asm("{ .reg .u64 t; cvta.to.shared.u64 t, %1; cvt.u32.u64 %0, t; }" : "=r"(a) : "l"(p));
    return a;
}
__device__ __forceinline__ uint32_t pack_h2(float lo, float hi) {
    uint32_t r; asm("cvt.rn.f16x2.f32 %0, %1, %2;" : "=r"(r) : "f"(hi), "f"(lo)); return r;
}
__device__ __forceinline__ void ldsm_x4(uint32_t* r, uint32_t a) {
    asm volatile("ldmatrix.sync.aligned.m8n8.x4.shared.b16 {%0,%1,%2,%3}, [%4];"
        : "=r"(r[0]), "=r"(r[1]), "=r"(r[2]), "=r"(r[3]) : "r"(a));
}
__device__ __forceinline__ void ldsm_x4t(uint32_t* r, uint32_t a) {
    asm volatile("ldmatrix.sync.aligned.m8n8.x4.trans.shared.b16 {%0,%1,%2,%3}, [%4];"
        : "=r"(r[0]), "=r"(r[1]), "=r"(r[2]), "=r"(r[3]) : "r"(a));
}
__device__ __forceinline__ void mma16816(float* d, const uint32_t* a, const uint32_t* b) {
    asm volatile("mma.sync.aligned.m16n8k16.row.col.f32.f16.f16.f32 "
        "{%0,%1,%2,%3}, {%4,%5,%6,%7}, {%8,%9}, {%0,%1,%2,%3};"
        : "+f"(d[0]), "+f"(d[1]), "+f"(d[2]), "+f"(d[3])
        : "r"(a[0]), "r"(a[1]), "r"(a[2]), "r"(a[3]), "r"(b[0]), "r"(b[1]));
}
__device__ __forceinline__ float shflx(float v, int m) {
    return __shfl_xor_sync(0xffffffffu, v, m);
}
__device__ __forceinline__ void cpa16(uint32_t s, const void* g) {
    asm volatile("cp.async.cg.shared.global [%0], [%1], 16;" :: "r"(s), "l"(g));
}
#define CP_COMMIT() asm volatile("cp.async.commit_group;" ::: "memory")
#define CP_WAIT0()  asm volatile("cp.async.wait_group 0;" ::: "memory")
#define CP_WAIT1()  asm volatile("cp.async.wait_group 1;" ::: "memory")

// ------------------- prep kernels (unchanged) -------------------
__global__ void __launch_bounds__(256)
split_w_kernel(const float* __restrict__ wq, const float* __restrict__ wk, const float* __restrict__ wv)
{
    __shared__ float t[32][33];
    const int sel = blockIdx.z;
    const float* W = (sel == 0) ? wq : (sel == 1) ? wk : wv;
    __half* dh = g_wh + sel * C_DIM * C_DIM;
    __half* dl = g_wl + sel * C_DIM * C_DIM;
    const int o0 = blockIdx.x * 32, c0 = blockIdx.y * 32;
    const int tx = threadIdx.x, ty = threadIdx.y;
    #pragma unroll
    for (int i = 0; i < 4; i++)
        t[ty + 8 * i][tx] = W[(o0 + ty + 8 * i) * C_DIM + c0 + tx];
    __syncthreads();
    #pragma unroll
    for (int i = 0; i < 4; i++) {
        float v = t[tx][ty + 8 * i];
        __half h = __float2half_rn(v);
        int o = (c0 + ty + 8 * i) * C_DIM + o0 + tx;
        dh[o] = h;
        dl[o] = __float2half_rn(v - __half2float(h));
    }
}

__global__ void __launch_bounds__(256)
split_wo_kernel(const float* __restrict__ wo)
{
    int i = blockIdx.x * 256 + threadIdx.x;
    const float2 v = ((const float2*)wo)[i];
    __half2 h = __floats2half2_rn(v.x, v.y);
    float2 hf = __half22float2(h);
    ((__half2*)g_woh)[i] = h;
    ((__half2*)g_wol)[i] = __floats2half2_rn(v.x - hf.x, v.y - hf.y);
}

__global__ void __launch_bounds__(256)
convert_x_kernel(const float* __restrict__ x)
{
    __shared__ float t[32][33];
    const int b = blockIdx.z;
    const float* src = x + (size_t)b * C_DIM * L_DIM;
    __half* dh = g_xth + (size_t)b * L_DIM * C_DIM;
    __half* dl = g_xtl + (size_t)b * L_DIM * C_DIM;
    const int l0 = blockIdx.x * 32, c0 = blockIdx.y * 32;
    const int tx = threadIdx.x, ty = threadIdx.y;
    #pragma unroll
    for (int i = 0; i < 4; i++)
        t[ty + 8 * i][tx] = src[(size_t)(c0 + ty + 8 * i) * L_DIM + l0 + tx];
    __syncthreads();
    #pragma unroll
    for (int i = 0; i < 4; i++) {
        float v = t[tx][ty + 8 * i];
        __half h = __float2half_rn(v);
        size_t o = (size_t)(l0 + ty + 8 * i) * C_DIM + c0 + tx;
        dh[o] = h;
        dl[o] = __float2half_rn(v - __half2float(h));
    }
}

// ------------------- mma QKV projection: 128x128 tiles, 3-stage cp.async -------------------
// stage (halves): AH 0 (5120), AL 5120, BH 10240 (4352), BL 14592; stage = 18944
#define PJ_STAGE 18944
#define PJ_BYTES (3 * PJ_STAGE * 2)

__global__ void __launch_bounds__(256)
proj_qkv_mma_kernel(const float* __restrict__ bq, const float* __restrict__ bk,
                    const float* __restrict__ bv)
{
    extern __shared__ __half dynsm[];
    __shared__ float bias_s[128];

    const int tid = threadIdx.x, lane = tid & 31, w = tid >> 5;
    const int lt = blockIdx.x >> 1, oh = blockIdx.x & 1;
    const int sel = blockIdx.y, b = blockIdx.z;

    const __half* xh = g_xth + (size_t)b * L_DIM * C_DIM;
    const __half* xl = g_xtl + (size_t)b * L_DIM * C_DIM;
    const __half* wh = g_wh + sel * C_DIM * C_DIM;
    const __half* wl = g_wl + sel * C_DIM * C_DIM;
    const float* bias = (sel == 0) ? bq : (sel == 1) ? bk : bv;
    __half* Yh = (sel == 0) ? g_qh : (sel == 1) ? g_kth : g_vth;
    __half* Yl = (sel == 0) ? (__half*)0 : (sel == 1) ? g_ktl : g_vtl;
    const float sc = (sel == 0) ? (SCALE * LOG2E) : 1.0f;

    if (tid < 128) bias_s[tid] = bias[oh * 128 + tid];

    const int arow = tid >> 2, aseg = tid & 3;
    const int brow = tid >> 4, bseg = tid & 15;

    // prologue: stages 0 and 1
    #pragma unroll
    for (int s = 0; s < 2; s++) {
        __half* base = dynsm + s * PJ_STAGE;
        int kc0 = s * 32;
        #pragma unroll
        for (int i = 0; i < 2; i++) {
            int row = arow + i * 64;
            size_t g = (size_t)(lt * 128 + row) * C_DIM + kc0 + aseg * 8;
            cpa16(smem_u32(base + row * 40 + aseg * 8), &xh[g]);
            cpa16(smem_u32(base + 5120 + row * 40 + aseg * 8), &xl[g]);
        }
        #pragma unroll
        for (int i = 0; i < 2; i++) {
            int row = brow + i * 16;
            int g = (kc0 + row) * C_DIM + oh * 128 + bseg * 8;
            cpa16(smem_u32(base + 10240 + row * 136 + bseg * 8), &wh[g]);
            cpa16(smem_u32(base + 14592 + row * 136 + bseg * 8), &wl[g]);
        }
        CP_COMMIT();
    }

    float acc[16][4] = {};
    const int rr = lane & 15;
    const int chi = (lane & 16) ? 8 : 0;

    for (int it = 0; it < 8; it++) {
        if (it == 7) { CP_WAIT0(); } else { CP_WAIT1(); }
        __syncthreads();

        if (it < 6) {
            __half* base = dynsm + ((it + 2) % 3) * PJ_STAGE;
            int kc0 = (it + 2) * 32;
            #pragma unroll
            for (int i = 0; i < 2; i++) {
                int row = arow + i * 64;
                size_t g = (size_t)(lt * 128 + row) * C_DIM + kc0 + aseg * 8;
                cpa16(smem_u32(base + row * 40 + aseg * 8), &xh[g]);
                cpa16(smem_u32(base + 5120 + row * 40 + aseg * 8), &xl[g]);
            }
            #pragma unroll
            for (int i = 0; i < 2; i++) {
                int row = brow + i * 16;
                int g = (kc0 + row) * C_DIM + oh * 128 + bseg * 8;
                cpa16(smem_u32(base + 10240 + row * 136 + bseg * 8), &wh[g]);
                cpa16(smem_u32(base + 14592 + row * 136 + bseg * 8), &wl[g]);
            }
            CP_COMMIT();
        }

        __half* cur = dynsm + (it % 3) * PJ_STAGE;
        __half* ah = cur;
        __half* al = cur + 5120;
        __half* bh_s = cur + 10240;
        __half* bl_s = cur + 14592;

        uint32_t af[2][2][4];
        #pragma unroll
        for (int kc = 0; kc < 2; kc++) {
            ldsm_x4(af[0][kc], smem_u32(&ah[(w * 16 + rr) * 40 + kc * 16 + chi]));
            ldsm_x4(af[1][kc], smem_u32(&al[(w * 16 + rr) * 40 + kc * 16 + chi]));
        }

        #pragma unroll
        for (int nt = 0; nt < 16; nt += 2) {
            #pragma unroll
            for (int kc = 0; kc < 2; kc++) {
                uint32_t bh[4], bl[4];
                ldsm_x4t(bh, smem_u32(&bh_s[(kc * 16 + rr) * 136 + nt * 8 + chi]));
                ldsm_x4t(bl, smem_u32(&bl_s[(kc * 16 + rr) * 136 + nt * 8 + chi]));
                mma16816(acc[nt],     af[0][kc], bh);
                mma16816(acc[nt + 1], af[0][kc], bh + 2);
                mma16816(acc[nt],     af[0][kc], bl);
                mma16816(acc[nt + 1], af[0][kc], bl + 2);
                mma16816(acc[nt],     af[1][kc], bh);
                mma16816(acc[nt + 1], af[1][kc], bh + 2);
            }
        }
    }

    // epilogue: write f16 hi (and lo, except for q) in [b][l][c]
    const int r0 = lt * 128 + w * 16 + (lane >> 2);
    #pragma unroll
    for (int nt = 0; nt < 16; nt++) {
        int c0 = nt * 8 + (lane & 3) * 2;
        float b0 = bias_s[c0], b1 = bias_s[c0 + 1];
        float v0 = (acc[nt][0] + b0) * sc, v1 = (acc[nt][1] + b1) * sc;
        float v2 = (acc[nt][2] + b0) * sc, v3 = (acc[nt][3] + b1) * sc;
        __half2 h0 = __floats2half2_rn(v0, v1);
        __half2 h1 = __floats2half2_rn(v2, v3);
        size_t o0 = (size_t)(b * 1024 + r0) * C_DIM + oh * 128 + c0;
        size_t o1 = (size_t)(b * 1024 + r0 + 8) * C_DIM + oh * 128 + c0;
        *(__half2*)&Yh[o0] = h0;
        *(__half2*)&Yh[o1] = h1;
        if (sel != 0) {
            float2 f0 = __half22float2(h0);
            float2 f1 = __half22float2(h1);
            *(__half2*)&Yl[o0] = __floats2half2_rn(v0 - f0.x, v1 - f0.y);
            *(__half2*)&Yl[o1] = __floats2half2_rn(v2 - f1.x, v3 - f1.y);
        }
    }
}

// ------------------- flash attention: no-max softmax (bounded base-2 logits) -------------------
// pool (halves): Q hi [0, 5120) (overlaid by buf1); buf1 = [0, 10240); buf0 = [10240, 20480)
// buffer layout: Kh +0, Kl +2560, Vh +5120, Vl +7680 (each 64 rows x pitch 40)
__global__ void __launch_bounds__(256, 2)
attn_mma_kernel()
{
    __shared__ __align__(16) __half pool[20480];

    const int tid = threadIdx.x, lane = tid & 31, w = tid >> 5;
    const int qt = blockIdx.x, n = blockIdx.y, b = blockIdx.z;
    const int rr = lane & 15;
    const int hoff = (lane & 16) ? 8 : 0;
    const int knr = (lane & 7) + ((lane >> 4) << 3);
    const int knc = ((lane >> 3) & 1) * 8;
    const int kvrow = tid >> 2, kvseg = tid & 3;

    {
        __half* base = pool + 10240;
        size_t g = ((size_t)(b * 1024 + kvrow)) * C_DIM + n * 32 + kvseg * 8;
        uint32_t s = smem_u32(base + kvrow * 40 + kvseg * 8);
        cpa16(s, &g_kth[g]);
        cpa16(s + 2560 * 2, &g_ktl[g]);
        cpa16(s + 5120 * 2, &g_vth[g]);
        cpa16(s + 7680 * 2, &g_vtl[g]);
        CP_COMMIT();
    }

    for (int u = tid; u < 512; u += 256) {
        int row = u >> 2, seg = u & 3;
        size_t g = ((size_t)(b * 1024 + qt * 128 + row)) * C_DIM + n * 32 + seg * 8;
        *(uint4*)&pool[row * 40 + seg * 8] = *(const uint4*)&g_qh[g];
    }
    __syncthreads();

    uint32_t qf[2][4];
    #pragma unroll
    for (int kc = 0; kc < 2; kc++)
        ldsm_x4(qf[kc], smem_u32(&pool[(w * 16 + rr) * 40 + kc * 16 + hoff]));
    __syncthreads();

    float oacc[4][4] = {};
    float l0 = 0.0f, l1 = 0.0f;

    for (int t = 0; t < 16; t++) {
        CP_WAIT0();
        __syncthreads();

        if (t < 15) {
            __half* base = pool + (((t + 1) & 1) ? 0 : 10240);
            size_t g = ((size_t)(b * 1024 + (t + 1) * 64 + kvrow)) * C_DIM + n * 32 + kvseg * 8;
            uint32_t s = smem_u32(base + kvrow * 40 + kvseg * 8);
            cpa16(s, &g_kth[g]);
            cpa16(s + 2560 * 2, &g_ktl[g]);
            cpa16(s + 5120 * 2, &g_vth[g]);
            cpa16(s + 7680 * 2, &g_vtl[g]);
            CP_COMMIT();
        }

        __half* cur = pool + ((t & 1) ? 0 : 10240);
        __half* ksh0 = cur;
        __half* ksh1 = cur + 2560;
        __half* vsh0 = cur + 5120;
        __half* vsh1 = cur + 7680;

        // ---- S = QhKh + QhKl ----
        float sacc[8][4];
        #pragma unroll
        for (int ntp = 0; ntp < 4; ntp++) {
            float* s0 = sacc[2 * ntp];
            float* s1 = sacc[2 * ntp + 1];
            s0[0] = s0[1] = s0[2] = s0[3] = 0.0f;
            s1[0] = s1[1] = s1[2] = s1[3] = 0.0f;
            #pragma unroll
            for (int kc = 0; kc < 2; kc++) {
                uint32_t off = (ntp * 16 + knr) * 40 + kc * 16 + knc;
                uint32_t kbh[4], kbl[4];
                ldsm_x4(kbh, smem_u32(&ksh0[off]));
                ldsm_x4(kbl, smem_u32(&ksh1[off]));
                mma16816(s0, qf[kc], kbh);
                mma16816(s1, qf[kc], kbh + 2);
                mma16816(s0, qf[kc], kbl);
                mma16816(s1, qf[kc], kbl + 2);
            }
        }

        // ---- softmax without max-subtraction (logits bounded; P <= ~2^11 fits f16) ----
        float rs0 = 0.0f, rs1 = 0.0f;
        #pragma unroll
        for (int nt = 0; nt < 8; nt++) {
            sacc[nt][0] = ex2f(sacc[nt][0]);
            sacc[nt][1] = ex2f(sacc[nt][1]);
            sacc[nt][2] = ex2f(sacc[nt][2]);
            sacc[nt][3] = ex2f(sacc[nt][3]);
            rs0 += sacc[nt][0] + sacc[nt][1];
            rs1 += sacc[nt][2] + sacc[nt][3];
        }
        rs0 += shflx(rs0, 1); rs0 += shflx(rs0, 2);
        rs1 += shflx(rs1, 1); rs1 += shflx(rs1, 2);
        l0 += rs0; l1 += rs1;

        // ---- P hi-only fragments ----
        uint32_t pfh[4][4];
        #pragma unroll
        for (int kc = 0; kc < 4; kc++) {
            const float* s0 = sacc[2 * kc];
            const float* s1 = sacc[2 * kc + 1];
            pfh[kc][0] = pack_h2(s0[0], s0[1]);
            pfh[kc][1] = pack_h2(s0[2], s0[3]);
            pfh[kc][2] = pack_h2(s1[0], s1[1]);
            pfh[kc][3] = pack_h2(s1[2], s1[3]);
        }

        // ---- O += Ph*Vh + Ph*Vl ----
        #pragma unroll
        for (int kc = 0; kc < 4; kc++) {
            #pragma unroll
            for (int np = 0; np < 2; np++) {
                uint32_t vbh[4], vbl[4];
                uint32_t off = (kc * 16 + rr) * 40 + np * 16 + hoff;
                ldsm_x4t(vbh, smem_u32(&vsh0[off]));
                ldsm_x4t(vbl, smem_u32(&vsh1[off]));
                mma16816(oacc[2 * np],     pfh[kc], vbh);
                mma16816(oacc[2 * np + 1], pfh[kc], vbh + 2);
                mma16816(oacc[2 * np],     pfh[kc], vbl);
                mma16816(oacc[2 * np + 1], pfh[kc], vbl + 2);
            }
        }
    }

    // ---- epilogue: O as f16 hi/lo split [b][c][l] ----
    float i0 = 1.0f / l0, i1 = 1.0f / l1;
    int q0 = qt * 128 + w * 16 + (lane >> 2);
    #pragma unroll
    for (int nt = 0; nt < 4; nt++) {
        int c = n * 32 + nt * 8 + (lane & 3) * 2;
        float v00 = oacc[nt][0] * i0, v01 = oacc[nt][1] * i0;
        float v10 = oacc[nt][2] * i1, v11 = oacc[nt][3] * i1;
        size_t b0 = ((size_t)(b * 256 + c)) * L_DIM + q0;
        size_t b1 = b0 + L_DIM;
        __half h;
        h = __float2half_rn(v00); g_xth[b0] = h;     g_xtl[b0] = __float2half_rn(v00 - __half2float(h));
        h = __float2half_rn(v01); g_xth[b1] = h;     g_xtl[b1] = __float2half_rn(v01 - __half2float(h));
        h = __float2half_rn(v10); g_xth[b0 + 8] = h; g_xtl[b0 + 8] = __float2half_rn(v10 - __half2float(h));
        h = __float2half_rn(v11); g_xth[b1 + 8] = h; g_xtl[b1 + 8] = __float2half_rn(v11 - __half2float(h));
    }
}

// ------------------- mma output projection: 128x128, 3-stage cp.async -------------------
__global__ void __launch_bounds__(256)
proj_o_mma_kernel(const float* __restrict__ bo, float* __restrict__ out)
{
    extern __shared__ __half dynsm[];
    __shared__ float bias_s[128];

    const int tid = threadIdx.x, lane = tid & 31, w = tid >> 5;
    const int lt = blockIdx.x >> 1, oh = blockIdx.x & 1;
    const int b = blockIdx.z;

    if (tid < 128) bias_s[tid] = bo[oh * 128 + tid];

    const int arow = tid >> 2, aseg = tid & 3;
    const int brow = tid >> 4, bseg = tid & 15;

    #pragma unroll
    for (int s = 0; s < 2; s++) {
        __half* base = dynsm + s * PJ_STAGE;
        int kc0 = s * 32;
        #pragma unroll
        for (int i = 0; i < 2; i++) {
            int row = arow + i * 64;
            int g = (oh * 128 + row) * C_DIM + kc0 + aseg * 8;
            cpa16(smem_u32(base + row * 40 + aseg * 8), &g_woh[g]);
            cpa16(smem_u32(base + 5120 + row * 40 + aseg * 8), &g_wol[g]);
        }
        #pragma unroll
        for (int i = 0; i < 2; i++) {
            int row = brow + i * 16;
            size_t g = ((size_t)(b * 256 + kc0 + row)) * L_DIM + lt * 128 + bseg * 8;
            cpa16(smem_u32(base + 10240 + row * 136 + bseg * 8), &g_xth[g]);
            cpa16(smem_u32(base + 14592 + row * 136 + bseg * 8), &g_xtl[g]);
        }
        CP_COMMIT();
    }

    float acc[16][4] = {};
    const int rr = lane & 15;
    const int chi = (lane & 16) ? 8 : 0;

    for (int it = 0; it < 8; it++) {
        if (it == 7) { CP_WAIT0(); } else { CP_WAIT1(); }
        __syncthreads();

        if (it < 6) {
            __half* base = dynsm + ((it + 2) % 3) * PJ_STAGE;
            int kc0 = (it + 2) * 32;
            #pragma unroll
            for (int i = 0; i < 2; i++) {
                int row = arow + i * 64;
                int g = (oh * 128 + row) * C_DIM + kc0 + aseg * 8;
                cpa16(smem_u32(base + row * 40 + aseg * 8), &g_woh[g]);
                cpa16(smem_u32(base + 5120 + row * 40 + aseg * 8), &g_wol[g]);
            }
            #pragma unroll
            for (int i = 0; i < 2; i++) {
                int row = brow + i * 16;
                size_t g = ((size_t)(b * 256 + kc0 + row)) * L_DIM + lt * 128 + bseg * 8;
                cpa16(smem_u32(base + 10240 + row * 136 + bseg * 8), &g_xth[g]);
                cpa16(smem_u32(base + 14592 + row * 136 + bseg * 8), &g_xtl[g]);
            }
            CP_COMMIT();
        }

        __half* cur = dynsm + (it % 3) * PJ_STAGE;
        __half* ah = cur;
        __half* al = cur + 5120;
        __half* bh_s = cur + 10240;
        __half* bl_s = cur + 14592;

        uint32_t af[2][2][4];
        #pragma unroll
        for (int kc = 0; kc < 2; kc++) {
            ldsm_x4(af[0][kc], smem_u32(&ah[(w * 16 + rr) * 40 + kc * 16 + chi]));
            ldsm_x4(af[1][kc], smem_u32(&al[(w * 16 + rr) * 40 + kc * 16 + chi]));
        }

        #pragma unroll
        for (int nt = 0; nt < 16; nt += 2) {
            #pragma unroll
            for (int kc = 0; kc < 2; kc++) {
                uint32_t bh[4], bl[4];
                ldsm_x4t(bh, smem_u32(&bh_s[(kc * 16 + rr) * 136 + nt * 8 + chi]));
                ldsm_x4t(bl, smem_u32(&bl_s[(kc * 16 + rr) * 136 + nt * 8 + chi]));
                mma16816(acc[nt],     af[0][kc], bh);
                mma16816(acc[nt + 1], af[0][kc], bh + 2);
                mma16816(acc[nt],     af[0][kc], bl);
                mma16816(acc[nt + 1], af[0][kc], bl + 2);
                mma16816(acc[nt],     af[1][kc], bh);
                mma16816(acc[nt + 1], af[1][kc], bh + 2);
            }
        }
    }

    const int orow = oh * 128 + w * 16 + (lane >> 2);
    const float bb0 = bias_s[w * 16 + (lane >> 2)];
    const float bb1 = bias_s[w * 16 + (lane >> 2) + 8];
    #pragma unroll
    for (int nt = 0; nt < 16; nt++) {
        int lcol = lt * 128 + nt * 8 + (lane & 3) * 2;
        float2 y0, y1;
        y0.x = acc[nt][0] + bb0; y0.y = acc[nt][1] + bb0;
        y1.x = acc[nt][2] + bb1; y1.y = acc[nt][3] + bb1;
        *(float2*)&out[((size_t)(b * 256 + orow)) * L_DIM + lcol] = y0;
        *(float2*)&out[((size_t)(b * 256 + orow + 8)) * L_DIM + lcol] = y1;
    }
}

// ---------------------------------------------------------------------------
extern "C" void kernel_launch(void* const* d_in, const int* in_sizes, int n_in,
                              void* d_out, int out_size)
{
    const float* x  = (const float*)d_in[0];
    const float* wq = (const float*)d_in[1];
    const float* bq = (const float*)d_in[2];
    const float* wk = (const float*)d_in[3];
    const float* bk = (const float*)d_in[4];
    const float* wv = (const float*)d_in[5];
    const float* bv = (const float*)d_in[6];
    const float* wo = (const float*)d_in[7];
    const float* bo = (const float*)d_in[8];
    float* out = (float*)d_out;

    cudaFuncSetAttribute(proj_qkv_mma_kernel, cudaFuncAttributeMaxDynamicSharedMemorySize, PJ_BYTES);
    cudaFuncSetAttribute(proj_o_mma_kernel, cudaFuncAttributeMaxDynamicSharedMemorySize, PJ_BYTES);

    split_w_kernel<<<dim3(8, 8, 3), dim3(32, 8)>>>(wq, wk, wv);
    split_wo_kernel<<<128, 256>>>(wo);
    convert_x_kernel<<<dim3(32, 8, 16), dim3(32, 8)>>>(x);
    proj_qkv_mma_kernel<<<dim3(16, 3, 16), 256, PJ_BYTES>>>(bq, bk, bv);
    attn_mma_kernel<<<dim3(8, 8, 16), 256>>>();
    proj_o_mma_kernel<<<dim3(16, 1, 16), 256, PJ_BYTES>>>(bo, out);
}

// round 14
// speedup vs baseline: 1.1724x; 1.0748x over previous
#include <cuda_runtime.h>
#include <cuda_fp16.h>
#include <cstdint>

#define C_DIM 256
#define L_DIM 1024
#define B_DIM 16
#define NH 8
#define DH 32
#define SCALE 0.17677669529663687f
#define LOG2E 1.4426950408889634f

// f16 hi/lo split buffers
__device__ __half g_qh[B_DIM * L_DIM * C_DIM];   // [b][l][c]
__device__ __half g_kth[B_DIM * L_DIM * C_DIM];  // k [b][l][c]
__device__ __half g_ktl[B_DIM * L_DIM * C_DIM];
__device__ __half g_vth[B_DIM * L_DIM * C_DIM];  // v [b][l][c]
__device__ __half g_vtl[B_DIM * L_DIM * C_DIM];
__device__ __half g_xth[B_DIM * L_DIM * C_DIM];  // x^T split; reused as att split [b][c][l]
__device__ __half g_xtl[B_DIM * L_DIM * C_DIM];
__device__ __half g_wh[3 * C_DIM * C_DIM];       // W^T [sel][c][o]
__device__ __half g_wl[3 * C_DIM * C_DIM];
__device__ __half g_woh[C_DIM * C_DIM];          // Wo [o][c]

__device__ __forceinline__ float ex2f(float x) {
    float r; asm("ex2.approx.f32 %0, %1;" : "=f"(r) : "f"(x)); return r;
}
__device__ __forceinline__ uint32_t smem_u32(const void* p) {
    uint32_t a;
    asm("{ .reg .u64 t; cvta.to.shared.u64 t, %1; cvt.u32.u64 %0, t; }" : "=r"(a) : "l"(p));
    return a;
}
__device__ __forceinline__ uint32_t pack_h2(float lo, float hi) {
    uint32_t r; asm("cvt.rn.f16x2.f32 %0, %1, %2;" : "=r"(r) : "f"(hi), "f"(lo)); return r;
}
__device__ __forceinline__ void ldsm_x4(uint32_t* r, uint32_t a) {
    asm volatile("ldmatrix.sync.aligned.m8n8.x4.shared.b16 {%0,%1,%2,%3}, [%4];"
        : "=r"(r[0]), "=r"(r[1]), "=r"(r[2]), "=r"(r[3]) : "r"(a));
}
__device__ __forceinline__ void ldsm_x4t(uint32_t* r, uint32_t a) {
    asm volatile("ldmatrix.sync.aligned.m8n8.x4.trans.shared.b16 {%0,%1,%2,%3}, [%4];"
        : "=r"(r[0]), "=r"(r[1]), "=r"(r[2]), "=r"(r[3]) : "r"(a));
}
__device__ __forceinline__ void mma16816(float* d, const uint32_t* a, const uint32_t* b) {
    asm volatile("mma.sync.aligned.m16n8k16.row.col.f32.f16.f16.f32 "
        "{%0,%1,%2,%3}, {%4,%5,%6,%7}, {%8,%9}, {%0,%1,%2,%3};"
        : "+f"(d[0]), "+f"(d[1]), "+f"(d[2]), "+f"(d[3])
        : "r"(a[0]), "r"(a[1]), "r"(a[2]), "r"(a[3]), "r"(b[0]), "r"(b[1]));
}
__device__ __forceinline__ float shflx(float v, int m) {
    return __shfl_xor_sync(0xffffffffu, v, m);
}
__device__ __forceinline__ void cpa16(uint32_t s, const void* g) {
    asm volatile("cp.async.cg.shared.global [%0], [%1], 16;" :: "r"(s), "l"(g));
}
#define CP_COMMIT() asm volatile("cp.async.commit_group;" ::: "memory")
#define CP_WAIT0()  asm volatile("cp.async.wait_group 0;" ::: "memory")

// ------------------- prep kernels -------------------
__global__ void __launch_bounds__(256)
split_w_kernel(const float* __restrict__ wq, const float* __restrict__ wk, const float* __restrict__ wv)
{
    __shared__ float t[32][33];
    const int sel = blockIdx.z;
    const float* W = (sel == 0) ? wq : (sel == 1) ? wk : wv;
    __half* dh = g_wh + sel * C_DIM * C_DIM;
    __half* dl = g_wl + sel * C_DIM * C_DIM;
    const int o0 = blockIdx.x * 32, c0 = blockIdx.y * 32;
    const int tx = threadIdx.x, ty = threadIdx.y;
    #pragma unroll
    for (int i = 0; i < 4; i++)
        t[ty + 8 * i][tx] = W[(o0 + ty + 8 * i) * C_DIM + c0 + tx];
    __syncthreads();
    #pragma unroll
    for (int i = 0; i < 4; i++) {
        float v = t[tx][ty + 8 * i];
        __half h = __float2half_rn(v);
        int o = (c0 + ty + 8 * i) * C_DIM + o0 + tx;
        dh[o] = h;
        dl[o] = __float2half_rn(v - __half2float(h));
    }
}

__global__ void __launch_bounds__(256)
split_wo_kernel(const float* __restrict__ wo)
{
    int i = blockIdx.x * 256 + threadIdx.x;
    const float2 v = ((const float2*)wo)[i];
    ((__half2*)g_woh)[i] = __floats2half2_rn(v.x, v.y);
}

__global__ void __launch_bounds__(256)
convert_x_kernel(const float* __restrict__ x)
{
    __shared__ float t[32][33];
    const int b = blockIdx.z;
    const float* src = x + (size_t)b * C_DIM * L_DIM;
    __half* dh = g_xth + (size_t)b * L_DIM * C_DIM;
    __half* dl = g_xtl + (size_t)b * L_DIM * C_DIM;
    const int l0 = blockIdx.x * 32, c0 = blockIdx.y * 32;
    const int tx = threadIdx.x, ty = threadIdx.y;
    #pragma unroll
    for (int i = 0; i < 4; i++)
        t[ty + 8 * i][tx] = src[(size_t)(c0 + ty + 8 * i) * L_DIM + l0 + tx];
    __syncthreads();
    #pragma unroll
    for (int i = 0; i < 4; i++) {
        float v = t[tx][ty + 8 * i];
        __half h = __float2half_rn(v);
        size_t o = (size_t)(l0 + ty + 8 * i) * C_DIM + c0 + tx;
        dh[o] = h;
        dl[o] = __float2half_rn(v - __half2float(h));
    }
}

// ------------------- mma QKV projection: 128x128, 2-stage (R11 shape) -------------------
// stage (halves): AH 0 (5120), AL 5120, BH 10240 (4352), BL 14592; stage = 18944
#define PJ_STAGE 18944
#define PJ_BYTES (2 * PJ_STAGE * 2)

__global__ void __launch_bounds__(256)
proj_qkv_mma_kernel(const float* __restrict__ bq, const float* __restrict__ bk,
                    const float* __restrict__ bv)
{
    extern __shared__ __half dynsm[];
    __shared__ float bias_s[128];

    const int tid = threadIdx.x, lane = tid & 31, w = tid >> 5;
    const int lt = blockIdx.x >> 1, oh = blockIdx.x & 1;
    const int sel = blockIdx.y, b = blockIdx.z;

    const __half* xh = g_xth + (size_t)b * L_DIM * C_DIM;
    const __half* xl = g_xtl + (size_t)b * L_DIM * C_DIM;
    const __half* wh = g_wh + sel * C_DIM * C_DIM;
    const __half* wl = g_wl + sel * C_DIM * C_DIM;
    const float* bias = (sel == 0) ? bq : (sel == 1) ? bk : bv;
    __half* Yh = (sel == 0) ? g_qh : (sel == 1) ? g_kth : g_vth;
    __half* Yl = (sel == 0) ? (__half*)0 : (sel == 1) ? g_ktl : g_vtl;
    const float sc = (sel == 0) ? (SCALE * LOG2E) : 1.0f;
    const bool full = (sel != 0);   // q: 2-term (xh*wh + xl*wh); k/v: 3-term

    if (tid < 128) bias_s[tid] = bias[oh * 128 + tid];

    const int arow = tid >> 2, aseg = tid & 3;
    const int brow = tid >> 4, bseg = tid & 15;

    {
        __half* base = dynsm;
        #pragma unroll
        for (int i = 0; i < 2; i++) {
            int row = arow + i * 64;
            size_t g = (size_t)(lt * 128 + row) * C_DIM + aseg * 8;
            cpa16(smem_u32(base + row * 40 + aseg * 8), &xh[g]);
            cpa16(smem_u32(base + 5120 + row * 40 + aseg * 8), &xl[g]);
        }
        #pragma unroll
        for (int i = 0; i < 2; i++) {
            int row = brow + i * 16;
            int g = row * C_DIM + oh * 128 + bseg * 8;
            cpa16(smem_u32(base + 10240 + row * 136 + bseg * 8), &wh[g]);
            if (full) cpa16(smem_u32(base + 14592 + row * 136 + bseg * 8), &wl[g]);
        }
        CP_COMMIT();
    }

    float acc[16][4] = {};
    const int rr = lane & 15;
    const int chi = (lane & 16) ? 8 : 0;

    for (int it = 0; it < 8; it++) {
        CP_WAIT0();
        __syncthreads();

        if (it < 7) {
            __half* base = dynsm + ((it + 1) & 1) * PJ_STAGE;
            int kc0 = (it + 1) * 32;
            #pragma unroll
            for (int i = 0; i < 2; i++) {
                int row = arow + i * 64;
                size_t g = (size_t)(lt * 128 + row) * C_DIM + kc0 + aseg * 8;
                cpa16(smem_u32(base + row * 40 + aseg * 8), &xh[g]);
                cpa16(smem_u32(base + 5120 + row * 40 + aseg * 8), &xl[g]);
            }
            #pragma unroll
            for (int i = 0; i < 2; i++) {
                int row = brow + i * 16;
                int g = (kc0 + row) * C_DIM + oh * 128 + bseg * 8;
                cpa16(smem_u32(base + 10240 + row * 136 + bseg * 8), &wh[g]);
                if (full) cpa16(smem_u32(base + 14592 + row * 136 + bseg * 8), &wl[g]);
            }
            CP_COMMIT();
        }

        __half* cur = dynsm + (it & 1) * PJ_STAGE;
        __half* ah = cur;
        __half* al = cur + 5120;
        __half* bh_s = cur + 10240;
        __half* bl_s = cur + 14592;

        uint32_t af[2][2][4];
        #pragma unroll
        for (int kc = 0; kc < 2; kc++) {
            ldsm_x4(af[0][kc], smem_u32(&ah[(w * 16 + rr) * 40 + kc * 16 + chi]));
            ldsm_x4(af[1][kc], smem_u32(&al[(w * 16 + rr) * 40 + kc * 16 + chi]));
        }

        if (full) {
            #pragma unroll
            for (int nt = 0; nt < 16; nt += 2) {
                #pragma unroll
                for (int kc = 0; kc < 2; kc++) {
                    uint32_t bh[4], bl[4];
                    ldsm_x4t(bh, smem_u32(&bh_s[(kc * 16 + rr) * 136 + nt * 8 + chi]));
                    ldsm_x4t(bl, smem_u32(&bl_s[(kc * 16 + rr) * 136 + nt * 8 + chi]));
                    mma16816(acc[nt],     af[0][kc], bh);
                    mma16816(acc[nt + 1], af[0][kc], bh + 2);
                    mma16816(acc[nt],     af[0][kc], bl);
                    mma16816(acc[nt + 1], af[0][kc], bl + 2);
                    mma16816(acc[nt],     af[1][kc], bh);
                    mma16816(acc[nt + 1], af[1][kc], bh + 2);
                }
            }
        } else {
            #pragma unroll
            for (int nt = 0; nt < 16; nt += 2) {
                #pragma unroll
                for (int kc = 0; kc < 2; kc++) {
                    uint32_t bh[4];
                    ldsm_x4t(bh, smem_u32(&bh_s[(kc * 16 + rr) * 136 + nt * 8 + chi]));
                    mma16816(acc[nt],     af[0][kc], bh);
                    mma16816(acc[nt + 1], af[0][kc], bh + 2);
                    mma16816(acc[nt],     af[1][kc], bh);
                    mma16816(acc[nt + 1], af[1][kc], bh + 2);
                }
            }
        }
    }

    // epilogue: write f16 hi (and lo, except for q) in [b][l][c]
    const int r0 = lt * 128 + w * 16 + (lane >> 2);
    #pragma unroll
    for (int nt = 0; nt < 16; nt++) {
        int c0 = nt * 8 + (lane & 3) * 2;
        float b0 = bias_s[c0], b1 = bias_s[c0 + 1];
        float v0 = (acc[nt][0] + b0) * sc, v1 = (acc[nt][1] + b1) * sc;
        float v2 = (acc[nt][2] + b0) * sc, v3 = (acc[nt][3] + b1) * sc;
        __half2 h0 = __floats2half2_rn(v0, v1);
        __half2 h1 = __floats2half2_rn(v2, v3);
        size_t o0 = (size_t)(b * 1024 + r0) * C_DIM + oh * 128 + c0;
        size_t o1 = (size_t)(b * 1024 + r0 + 8) * C_DIM + oh * 128 + c0;
        *(__half2*)&Yh[o0] = h0;
        *(__half2*)&Yh[o1] = h1;
        if (sel != 0) {
            float2 f0 = __half22float2(h0);
            float2 f1 = __half22float2(h1);
            *(__half2*)&Yl[o0] = __floats2half2_rn(v0 - f0.x, v1 - f0.y);
            *(__half2*)&Yl[o1] = __floats2half2_rn(v2 - f1.x, v3 - f1.y);
        }
    }
}

// ------------------- flash attention (byte-identical to R13 win) -------------------
__global__ void __launch_bounds__(256, 2)
attn_mma_kernel()
{
    __shared__ __align__(16) __half pool[20480];

    const int tid = threadIdx.x, lane = tid & 31, w = tid >> 5;
    const int qt = blockIdx.x, n = blockIdx.y, b = blockIdx.z;
    const int rr = lane & 15;
    const int hoff = (lane & 16) ? 8 : 0;
    const int knr = (lane & 7) + ((lane >> 4) << 3);
    const int knc = ((lane >> 3) & 1) * 8;
    const int kvrow = tid >> 2, kvseg = tid & 3;

    {
        __half* base = pool + 10240;
        size_t g = ((size_t)(b * 1024 + kvrow)) * C_DIM + n * 32 + kvseg * 8;
        uint32_t s = smem_u32(base + kvrow * 40 + kvseg * 8);
        cpa16(s, &g_kth[g]);
        cpa16(s + 2560 * 2, &g_ktl[g]);
        cpa16(s + 5120 * 2, &g_vth[g]);
        cpa16(s + 7680 * 2, &g_vtl[g]);
        CP_COMMIT();
    }

    for (int u = tid; u < 512; u += 256) {
        int row = u >> 2, seg = u & 3;
        size_t g = ((size_t)(b * 1024 + qt * 128 + row)) * C_DIM + n * 32 + seg * 8;
        *(uint4*)&pool[row * 40 + seg * 8] = *(const uint4*)&g_qh[g];
    }
    __syncthreads();

    uint32_t qf[2][4];
    #pragma unroll
    for (int kc = 0; kc < 2; kc++)
        ldsm_x4(qf[kc], smem_u32(&pool[(w * 16 + rr) * 40 + kc * 16 + hoff]));
    __syncthreads();

    float oacc[4][4] = {};
    float l0 = 0.0f, l1 = 0.0f;

    for (int t = 0; t < 16; t++) {
        CP_WAIT0();
        __syncthreads();

        if (t < 15) {
            __half* base = pool + (((t + 1) & 1) ? 0 : 10240);
            size_t g = ((size_t)(b * 1024 + (t + 1) * 64 + kvrow)) * C_DIM + n * 32 + kvseg * 8;
            uint32_t s = smem_u32(base + kvrow * 40 + kvseg * 8);
            cpa16(s, &g_kth[g]);
            cpa16(s + 2560 * 2, &g_ktl[g]);
            cpa16(s + 5120 * 2, &g_vth[g]);
            cpa16(s + 7680 * 2, &g_vtl[g]);
            CP_COMMIT();
        }

        __half* cur = pool + ((t & 1) ? 0 : 10240);
        __half* ksh0 = cur;
        __half* ksh1 = cur + 2560;
        __half* vsh0 = cur + 5120;
        __half* vsh1 = cur + 7680;

        float sacc[8][4];
        #pragma unroll
        for (int ntp = 0; ntp < 4; ntp++) {
            float* s0 = sacc[2 * ntp];
            float* s1 = sacc[2 * ntp + 1];
            s0[0] = s0[1] = s0[2] = s0[3] = 0.0f;
            s1[0] = s1[1] = s1[2] = s1[3] = 0.0f;
            #pragma unroll
            for (int kc = 0; kc < 2; kc++) {
                uint32_t off = (ntp * 16 + knr) * 40 + kc * 16 + knc;
                uint32_t kbh[4], kbl[4];
                ldsm_x4(kbh, smem_u32(&ksh0[off]));
                ldsm_x4(kbl, smem_u32(&ksh1[off]));
                mma16816(s0, qf[kc], kbh);
                mma16816(s1, qf[kc], kbh + 2);
                mma16816(s0, qf[kc], kbl);
                mma16816(s1, qf[kc], kbl + 2);
            }
        }

        float rs0 = 0.0f, rs1 = 0.0f;
        #pragma unroll
        for (int nt = 0; nt < 8; nt++) {
            sacc[nt][0] = ex2f(sacc[nt][0]);
            sacc[nt][1] = ex2f(sacc[nt][1]);
            sacc[nt][2] = ex2f(sacc[nt][2]);
            sacc[nt][3] = ex2f(sacc[nt][3]);
            rs0 += sacc[nt][0] + sacc[nt][1];
            rs1 += sacc[nt][2] + sacc[nt][3];
        }
        rs0 += shflx(rs0, 1); rs0 += shflx(rs0, 2);
        rs1 += shflx(rs1, 1); rs1 += shflx(rs1, 2);
        l0 += rs0; l1 += rs1;

        uint32_t pfh[4][4];
        #pragma unroll
        for (int kc = 0; kc < 4; kc++) {
            const float* s0 = sacc[2 * kc];
            const float* s1 = sacc[2 * kc + 1];
            pfh[kc][0] = pack_h2(s0[0], s0[1]);
            pfh[kc][1] = pack_h2(s0[2], s0[3]);
            pfh[kc][2] = pack_h2(s1[0], s1[1]);
            pfh[kc][3] = pack_h2(s1[2], s1[3]);
        }

        #pragma unroll
        for (int kc = 0; kc < 4; kc++) {
            #pragma unroll
            for (int np = 0; np < 2; np++) {
                uint32_t vbh[4], vbl[4];
                uint32_t off = (kc * 16 + rr) * 40 + np * 16 + hoff;
                ldsm_x4t(vbh, smem_u32(&vsh0[off]));
                ldsm_x4t(vbl, smem_u32(&vsh1[off]));
                mma16816(oacc[2 * np],     pfh[kc], vbh);
                mma16816(oacc[2 * np + 1], pfh[kc], vbh + 2);
                mma16816(oacc[2 * np],     pfh[kc], vbl);
                mma16816(oacc[2 * np + 1], pfh[kc], vbl + 2);
            }
        }
    }

    float i0 = 1.0f / l0, i1 = 1.0f / l1;
    int q0 = qt * 128 + w * 16 + (lane >> 2);
    #pragma unroll
    for (int nt = 0; nt < 4; nt++) {
        int c = n * 32 + nt * 8 + (lane & 3) * 2;
        float v00 = oacc[nt][0] * i0, v01 = oacc[nt][1] * i0;
        float v10 = oacc[nt][2] * i1, v11 = oacc[nt][3] * i1;
        size_t b0 = ((size_t)(b * 256 + c)) * L_DIM + q0;
        size_t b1 = b0 + L_DIM;
        __half h;
        h = __float2half_rn(v00); g_xth[b0] = h;     g_xtl[b0] = __float2half_rn(v00 - __half2float(h));
        h = __float2half_rn(v01); g_xth[b1] = h;     g_xtl[b1] = __float2half_rn(v01 - __half2float(h));
        h = __float2half_rn(v10); g_xth[b0 + 8] = h; g_xtl[b0 + 8] = __float2half_rn(v10 - __half2float(h));
        h = __float2half_rn(v11); g_xth[b1 + 8] = h; g_xtl[b1 + 8] = __float2half_rn(v11 - __half2float(h));
    }
}

// ------------------- mma output projection: 128x128, 2-stage, Wo hi-only -------------------
// stage (halves): AH 0 (5120), BH 5120 (4352), BL 9472; stage = 13824
#define PO_STAGE 13824
#define PO_BYTES (2 * PO_STAGE * 2)

__global__ void __launch_bounds__(256)
proj_o_mma_kernel(const float* __restrict__ bo, float* __restrict__ out)
{
    extern __shared__ __half dynsm[];
    __shared__ float bias_s[128];

    const int tid = threadIdx.x, lane = tid & 31, w = tid >> 5;
    const int lt = blockIdx.x >> 1, oh = blockIdx.x & 1;
    const int b = blockIdx.z;

    if (tid < 128) bias_s[tid] = bo[oh * 128 + tid];

    const int arow = tid >> 2, aseg = tid & 3;
    const int brow = tid >> 4, bseg = tid & 15;

    {
        __half* base = dynsm;
        #pragma unroll
        for (int i = 0; i < 2; i++) {
            int row = arow + i * 64;
            int g = (oh * 128 + row) * C_DIM + aseg * 8;
            cpa16(smem_u32(base + row * 40 + aseg * 8), &g_woh[g]);
        }
        #pragma unroll
        for (int i = 0; i < 2; i++) {
            int row = brow + i * 16;
            size_t g = ((size_t)(b * 256 + row)) * L_DIM + lt * 128 + bseg * 8;
            cpa16(smem_u32(base + 5120 + row * 136 + bseg * 8), &g_xth[g]);
            cpa16(smem_u32(base + 9472 + row * 136 + bseg * 8), &g_xtl[g]);
        }
        CP_COMMIT();
    }

    float acc[16][4] = {};
    const int rr = lane & 15;
    const int chi = (lane & 16) ? 8 : 0;

    for (int it = 0; it < 8; it++) {
        CP_WAIT0();
        __syncthreads();

        if (it < 7) {
            __half* base = dynsm + ((it + 1) & 1) * PO_STAGE;
            int kc0 = (it + 1) * 32;
            #pragma unroll
            for (int i = 0; i < 2; i++) {
                int row = arow + i * 64;
                int g = (oh * 128 + row) * C_DIM + kc0 + aseg * 8;
                cpa16(smem_u32(base + row * 40 + aseg * 8), &g_woh[g]);
            }
            #pragma unroll
            for (int i = 0; i < 2; i++) {
                int row = brow + i * 16;
                size_t g = ((size_t)(b * 256 + kc0 + row)) * L_DIM + lt * 128 + bseg * 8;
                cpa16(smem_u32(base + 5120 + row * 136 + bseg * 8), &g_xth[g]);
                cpa16(smem_u32(base + 9472 + row * 136 + bseg * 8), &g_xtl[g]);
            }
            CP_COMMIT();
        }

        __half* cur = dynsm + (it & 1) * PO_STAGE;
        __half* ah = cur;
        __half* bh_s = cur + 5120;
        __half* bl_s = cur + 9472;

        uint32_t af[2][4];
        #pragma unroll
        for (int kc = 0; kc < 2; kc++)
            ldsm_x4(af[kc], smem_u32(&ah[(w * 16 + rr) * 40 + kc * 16 + chi]));

        #pragma unroll
        for (int nt = 0; nt < 16; nt += 2) {
            #pragma unroll
            for (int kc = 0; kc < 2; kc++) {
                uint32_t bh[4], bl[4];
                ldsm_x4t(bh, smem_u32(&bh_s[(kc * 16 + rr) * 136 + nt * 8 + chi]));
                ldsm_x4t(bl, smem_u32(&bl_s[(kc * 16 + rr) * 136 + nt * 8 + chi]));
                mma16816(acc[nt],     af[kc], bh);
                mma16816(acc[nt + 1], af[kc], bh + 2);
                mma16816(acc[nt],     af[kc], bl);
                mma16816(acc[nt + 1], af[kc], bl + 2);
            }
        }
    }

    const int orow = oh * 128 + w * 16 + (lane >> 2);
    const float bb0 = bias_s[w * 16 + (lane >> 2)];
    const float bb1 = bias_s[w * 16 + (lane >> 2) + 8];
    #pragma unroll
    for (int nt = 0; nt < 16; nt++) {
        int lcol = lt * 128 + nt * 8 + (lane & 3) * 2;
        float2 y0, y1;
        y0.x = acc[nt][0] + bb0; y0.y = acc[nt][1] + bb0;
        y1.x = acc[nt][2] + bb1; y1.y = acc[nt][3] + bb1;
        *(float2*)&out[((size_t)(b * 256 + orow)) * L_DIM + lcol] = y0;
        *(float2*)&out[((size_t)(b * 256 + orow + 8)) * L_DIM + lcol] = y1;
    }
}

// ---------------------------------------------------------------------------
extern "C" void kernel_launch(void* const* d_in, const int* in_sizes, int n_in,
                              void* d_out, int out_size)
{
    const float* x  = (const float*)d_in[0];
    const float* wq = (const float*)d_in[1];
    const float* bq = (const float*)d_in[2];
    const float* wk = (const float*)d_in[3];
    const float* bk = (const float*)d_in[4];
    const float* wv = (const float*)d_in[5];
    const float* bv = (const float*)d_in[6];
    const float* wo = (const float*)d_in[7];
    const float* bo = (const float*)d_in[8];
    float* out = (float*)d_out;

    cudaFuncSetAttribute(proj_qkv_mma_kernel, cudaFuncAttributeMaxDynamicSharedMemorySize, PJ_BYTES);
    cudaFuncSetAttribute(proj_o_mma_kernel, cudaFuncAttributeMaxDynamicSharedMemorySize, PO_BYTES);

    split_w_kernel<<<dim3(8, 8, 3), dim3(32, 8)>>>(wq, wk, wv);
    split_wo_kernel<<<128, 256>>>(wo);
    convert_x_kernel<<<dim3(32, 8, 16), dim3(32, 8)>>>(x);
    proj_qkv_mma_kernel<<<dim3(16, 3, 16), 256, PJ_BYTES>>>(bq, bk, bv);
    attn_mma_kernel<<<dim3(8, 8, 16), 256>>>();
    proj_o_mma_kernel<<<dim3(16, 1, 16), 256, PO_BYTES>>>(bo, out);
}

// round 15
// speedup vs baseline: 1.1955x; 1.0197x over previous
#include <cuda_runtime.h>
#include <cuda_fp16.h>
#include <cstdint>

#define C_DIM 256
#define L_DIM 1024
#define B_DIM 16
#define NH 8
#define DH 32
#define SCALE 0.17677669529663687f
#define LOG2E 1.4426950408889634f

// f16 hi/lo split buffers
__device__ __half g_qh[B_DIM * L_DIM * C_DIM];   // [b][l][c]
__device__ __half g_kth[B_DIM * L_DIM * C_DIM];  // k [b][l][c]
__device__ __half g_ktl[B_DIM * L_DIM * C_DIM];
__device__ __half g_vth[B_DIM * L_DIM * C_DIM];  // v [b][l][c]
__device__ __half g_vtl[B_DIM * L_DIM * C_DIM];
__device__ __half g_xth[B_DIM * L_DIM * C_DIM];  // x^T split; reused as att split [b][c][l]
__device__ __half g_xtl[B_DIM * L_DIM * C_DIM];
__device__ __half g_wh[3 * C_DIM * C_DIM];       // W^T [sel][c][o]
__device__ __half g_wl[3 * C_DIM * C_DIM];
__device__ __half g_woh[C_DIM * C_DIM];          // Wo [o][c]

__device__ __forceinline__ float ex2f(float x) {
    float r; asm("ex2.approx.f32 %0, %1;" : "=f"(r) : "f"(x)); return r;
}
__device__ __forceinline__ uint32_t smem_u32(const void* p) {
    uint32_t a;
    asm("{ .reg .u64 t; cvta.to.shared.u64 t, %1; cvt.u32.u64 %0, t; }" : "=r"(a) : "l"(p));
    return a;
}
__device__ __forceinline__ uint32_t pack_h2(float lo, float hi) {
    uint32_t r; asm("cvt.rn.f16x2.f32 %0, %1, %2;" : "=r"(r) : "f"(hi), "f"(lo)); return r;
}
__device__ __forceinline__ void ldsm_x4(uint32_t* r, uint32_t a) {
    asm volatile("ldmatrix.sync.aligned.m8n8.x4.shared.b16 {%0,%1,%2,%3}, [%4];"
        : "=r"(r[0]), "=r"(r[1]), "=r"(r[2]), "=r"(r[3]) : "r"(a));
}
__device__ __forceinline__ void ldsm_x4t(uint32_t* r, uint32_t a) {
    asm volatile("ldmatrix.sync.aligned.m8n8.x4.trans.shared.b16 {%0,%1,%2,%3}, [%4];"
        : "=r"(r[0]), "=r"(r[1]), "=r"(r[2]), "=r"(r[3]) : "r"(a));
}
__device__ __forceinline__ void mma16816(float* d, const uint32_t* a, const uint32_t* b) {
    asm volatile("mma.sync.aligned.m16n8k16.row.col.f32.f16.f16.f32 "
        "{%0,%1,%2,%3}, {%4,%5,%6,%7}, {%8,%9}, {%0,%1,%2,%3};"
        : "+f"(d[0]), "+f"(d[1]), "+f"(d[2]), "+f"(d[3])
        : "r"(a[0]), "r"(a[1]), "r"(a[2]), "r"(a[3]), "r"(b[0]), "r"(b[1]));
}
__device__ __forceinline__ float shflx(float v, int m) {
    return __shfl_xor_sync(0xffffffffu, v, m);
}
__device__ __forceinline__ void cpa16(uint32_t s, const void* g) {
    asm volatile("cp.async.cg.shared.global [%0], [%1], 16;" :: "r"(s), "l"(g));
}
#define CP_COMMIT() asm volatile("cp.async.commit_group;" ::: "memory")
#define CP_WAIT0()  asm volatile("cp.async.wait_group 0;" ::: "memory")

// ------------------- prep kernels -------------------
__global__ void __launch_bounds__(256)
split_w_kernel(const float* __restrict__ wq, const float* __restrict__ wk, const float* __restrict__ wv)
{
    __shared__ float t[32][33];
    const int sel = blockIdx.z;
    const float* W = (sel == 0) ? wq : (sel == 1) ? wk : wv;
    __half* dh = g_wh + sel * C_DIM * C_DIM;
    __half* dl = g_wl + sel * C_DIM * C_DIM;
    const int o0 = blockIdx.x * 32, c0 = blockIdx.y * 32;
    const int tx = threadIdx.x, ty = threadIdx.y;
    #pragma unroll
    for (int i = 0; i < 4; i++)
        t[ty + 8 * i][tx] = W[(o0 + ty + 8 * i) * C_DIM + c0 + tx];
    __syncthreads();
    #pragma unroll
    for (int i = 0; i < 4; i++) {
        float v = t[tx][ty + 8 * i];
        __half h = __float2half_rn(v);
        int o = (c0 + ty + 8 * i) * C_DIM + o0 + tx;
        dh[o] = h;
        dl[o] = __float2half_rn(v - __half2float(h));
    }
}

__global__ void __launch_bounds__(256)
split_wo_kernel(const float* __restrict__ wo)
{
    int i = blockIdx.x * 256 + threadIdx.x;
    const float2 v = ((const float2*)wo)[i];
    ((__half2*)g_woh)[i] = __floats2half2_rn(v.x, v.y);
}

__global__ void __launch_bounds__(256)
convert_x_kernel(const float* __restrict__ x)
{
    __shared__ float t[32][33];
    const int b = blockIdx.z;
    const float* src = x + (size_t)b * C_DIM * L_DIM;
    __half* dh = g_xth + (size_t)b * L_DIM * C_DIM;
    __half* dl = g_xtl + (size_t)b * L_DIM * C_DIM;
    const int l0 = blockIdx.x * 32, c0 = blockIdx.y * 32;
    const int tx = threadIdx.x, ty = threadIdx.y;
    #pragma unroll
    for (int i = 0; i < 4; i++)
        t[ty + 8 * i][tx] = src[(size_t)(c0 + ty + 8 * i) * L_DIM + l0 + tx];
    __syncthreads();
    #pragma unroll
    for (int i = 0; i < 4; i++) {
        float v = t[tx][ty + 8 * i];
        __half h = __float2half_rn(v);
        size_t o = (size_t)(l0 + ty + 8 * i) * C_DIM + c0 + tx;
        dh[o] = h;
        dl[o] = __float2half_rn(v - __half2float(h));
    }
}

// ------------------- shared projection constants -------------------
// kv stage (halves): AH 0 (5120), AL 5120, BH 10240 (4352), BL 14592; stage = 18944
#define PJ_STAGE 18944
#define PJ_BYTES (2 * PJ_STAGE * 2)
// q stage (halves): AH 0 (5120), AL 5120, BH 10240 (4352); stage = 14592
#define PQ_STAGE 14592
#define PQ_BYTES (2 * PQ_STAGE * 2)
// proj_o stage: AH 0 (5120), BH 5120 (4352), BL 9472; stage = 13824
#define PO_STAGE 13824
#define PO_BYTES (2 * PO_STAGE * 2)

// ------------------- q projection: 2-term (W * xh, W split) -------------------
__global__ void __launch_bounds__(256, 2)
proj_q_mma_kernel(const float* __restrict__ bq)
{
    extern __shared__ __half dynsm[];
    __shared__ float bias_s[128];

    const int tid = threadIdx.x, lane = tid & 31, w = tid >> 5;
    const int lt = blockIdx.x >> 1, oh = blockIdx.x & 1;
    const int b = blockIdx.z;

    const __half* xh = g_xth + (size_t)b * L_DIM * C_DIM;
    const __half* xl = g_xtl + (size_t)b * L_DIM * C_DIM;
    const __half* wh = g_wh;

    if (tid < 128) bias_s[tid] = bq[oh * 128 + tid];

    const int arow = tid >> 2, aseg = tid & 3;
    const int brow = tid >> 4, bseg = tid & 15;

    {
        __half* base = dynsm;
        #pragma unroll
        for (int i = 0; i < 2; i++) {
            int row = arow + i * 64;
            size_t g = (size_t)(lt * 128 + row) * C_DIM + aseg * 8;
            cpa16(smem_u32(base + row * 40 + aseg * 8), &xh[g]);
            cpa16(smem_u32(base + 5120 + row * 40 + aseg * 8), &xl[g]);
        }
        #pragma unroll
        for (int i = 0; i < 2; i++) {
            int row = brow + i * 16;
            cpa16(smem_u32(base + 10240 + row * 136 + bseg * 8), &wh[row * C_DIM + oh * 128 + bseg * 8]);
        }
        CP_COMMIT();
    }

    float acc[16][4] = {};
    const int rr = lane & 15;
    const int chi = (lane & 16) ? 8 : 0;

    for (int it = 0; it < 8; it++) {
        CP_WAIT0();
        __syncthreads();

        if (it < 7) {
            __half* base = dynsm + ((it + 1) & 1) * PQ_STAGE;
            int kc0 = (it + 1) * 32;
            #pragma unroll
            for (int i = 0; i < 2; i++) {
                int row = arow + i * 64;
                size_t g = (size_t)(lt * 128 + row) * C_DIM + kc0 + aseg * 8;
                cpa16(smem_u32(base + row * 40 + aseg * 8), &xh[g]);
                cpa16(smem_u32(base + 5120 + row * 40 + aseg * 8), &xl[g]);
            }
            #pragma unroll
            for (int i = 0; i < 2; i++) {
                int row = brow + i * 16;
                cpa16(smem_u32(base + 10240 + row * 136 + bseg * 8), &wh[(kc0 + row) * C_DIM + oh * 128 + bseg * 8]);
            }
            CP_COMMIT();
        }

        __half* cur = dynsm + (it & 1) * PQ_STAGE;
        __half* ah = cur;
        __half* al = cur + 5120;
        __half* bh_s = cur + 10240;

        uint32_t af[2][2][4];
        #pragma unroll
        for (int kc = 0; kc < 2; kc++) {
            ldsm_x4(af[0][kc], smem_u32(&ah[(w * 16 + rr) * 40 + kc * 16 + chi]));
            ldsm_x4(af[1][kc], smem_u32(&al[(w * 16 + rr) * 40 + kc * 16 + chi]));
        }

        #pragma unroll
        for (int nt = 0; nt < 16; nt += 2) {
            #pragma unroll
            for (int kc = 0; kc < 2; kc++) {
                uint32_t bh[4];
                ldsm_x4t(bh, smem_u32(&bh_s[(kc * 16 + rr) * 136 + nt * 8 + chi]));
                mma16816(acc[nt],     af[0][kc], bh);
                mma16816(acc[nt + 1], af[0][kc], bh + 2);
                mma16816(acc[nt],     af[1][kc], bh);
                mma16816(acc[nt + 1], af[1][kc], bh + 2);
            }
        }
    }

    const int r0 = lt * 128 + w * 16 + (lane >> 2);
    #pragma unroll
    for (int nt = 0; nt < 16; nt++) {
        int c0 = nt * 8 + (lane & 3) * 2;
        float b0 = bias_s[c0], b1 = bias_s[c0 + 1];
        float v0 = (acc[nt][0] + b0) * (SCALE * LOG2E), v1 = (acc[nt][1] + b1) * (SCALE * LOG2E);
        float v2 = (acc[nt][2] + b0) * (SCALE * LOG2E), v3 = (acc[nt][3] + b1) * (SCALE * LOG2E);
        size_t o0 = (size_t)(b * 1024 + r0) * C_DIM + oh * 128 + c0;
        size_t o1 = (size_t)(b * 1024 + r0 + 8) * C_DIM + oh * 128 + c0;
        *(__half2*)&g_qh[o0] = __floats2half2_rn(v0, v1);
        *(__half2*)&g_qh[o1] = __floats2half2_rn(v2, v3);
    }
}

// ------------------- k/v projection: 3-term -------------------
__global__ void __launch_bounds__(256, 2)
proj_kv_mma_kernel(const float* __restrict__ bk, const float* __restrict__ bv)
{
    extern __shared__ __half dynsm[];
    __shared__ float bias_s[128];

    const int tid = threadIdx.x, lane = tid & 31, w = tid >> 5;
    const int lt = blockIdx.x >> 1, oh = blockIdx.x & 1;
    const int sel = blockIdx.y + 1, b = blockIdx.z;   // 1 = k, 2 = v

    const __half* xh = g_xth + (size_t)b * L_DIM * C_DIM;
    const __half* xl = g_xtl + (size_t)b * L_DIM * C_DIM;
    const __half* wh = g_wh + sel * C_DIM * C_DIM;
    const __half* wl = g_wl + sel * C_DIM * C_DIM;
    const float* bias = (sel == 1) ? bk : bv;
    __half* Yh = (sel == 1) ? g_kth : g_vth;
    __half* Yl = (sel == 1) ? g_ktl : g_vtl;

    if (tid < 128) bias_s[tid] = bias[oh * 128 + tid];

    const int arow = tid >> 2, aseg = tid & 3;
    const int brow = tid >> 4, bseg = tid & 15;

    {
        __half* base = dynsm;
        #pragma unroll
        for (int i = 0; i < 2; i++) {
            int row = arow + i * 64;
            size_t g = (size_t)(lt * 128 + row) * C_DIM + aseg * 8;
            cpa16(smem_u32(base + row * 40 + aseg * 8), &xh[g]);
            cpa16(smem_u32(base + 5120 + row * 40 + aseg * 8), &xl[g]);
        }
        #pragma unroll
        for (int i = 0; i < 2; i++) {
            int row = brow + i * 16;
            int g = row * C_DIM + oh * 128 + bseg * 8;
            cpa16(smem_u32(base + 10240 + row * 136 + bseg * 8), &wh[g]);
            cpa16(smem_u32(base + 14592 + row * 136 + bseg * 8), &wl[g]);
        }
        CP_COMMIT();
    }

    float acc[16][4] = {};
    const int rr = lane & 15;
    const int chi = (lane & 16) ? 8 : 0;

    for (int it = 0; it < 8; it++) {
        CP_WAIT0();
        __syncthreads();

        if (it < 7) {
            __half* base = dynsm + ((it + 1) & 1) * PJ_STAGE;
            int kc0 = (it + 1) * 32;
            #pragma unroll
            for (int i = 0; i < 2; i++) {
                int row = arow + i * 64;
                size_t g = (size_t)(lt * 128 + row) * C_DIM + kc0 + aseg * 8;
                cpa16(smem_u32(base + row * 40 + aseg * 8), &xh[g]);
                cpa16(smem_u32(base + 5120 + row * 40 + aseg * 8), &xl[g]);
            }
            #pragma unroll
            for (int i = 0; i < 2; i++) {
                int row = brow + i * 16;
                int g = (kc0 + row) * C_DIM + oh * 128 + bseg * 8;
                cpa16(smem_u32(base + 10240 + row * 136 + bseg * 8), &wh[g]);
                cpa16(smem_u32(base + 14592 + row * 136 + bseg * 8), &wl[g]);
            }
            CP_COMMIT();
        }

        __half* cur = dynsm + (it & 1) * PJ_STAGE;
        __half* ah = cur;
        __half* al = cur + 5120;
        __half* bh_s = cur + 10240;
        __half* bl_s = cur + 14592;

        uint32_t af[2][2][4];
        #pragma unroll
        for (int kc = 0; kc < 2; kc++) {
            ldsm_x4(af[0][kc], smem_u32(&ah[(w * 16 + rr) * 40 + kc * 16 + chi]));
            ldsm_x4(af[1][kc], smem_u32(&al[(w * 16 + rr) * 40 + kc * 16 + chi]));
        }

        #pragma unroll
        for (int nt = 0; nt < 16; nt += 2) {
            #pragma unroll
            for (int kc = 0; kc < 2; kc++) {
                uint32_t bh[4], bl[4];
                ldsm_x4t(bh, smem_u32(&bh_s[(kc * 16 + rr) * 136 + nt * 8 + chi]));
                ldsm_x4t(bl, smem_u32(&bl_s[(kc * 16 + rr) * 136 + nt * 8 + chi]));
                mma16816(acc[nt],     af[0][kc], bh);
                mma16816(acc[nt + 1], af[0][kc], bh + 2);
                mma16816(acc[nt],     af[0][kc], bl);
                mma16816(acc[nt + 1], af[0][kc], bl + 2);
                mma16816(acc[nt],     af[1][kc], bh);
                mma16816(acc[nt + 1], af[1][kc], bh + 2);
            }
        }
    }

    const int r0 = lt * 128 + w * 16 + (lane >> 2);
    #pragma unroll
    for (int nt = 0; nt < 16; nt++) {
        int c0 = nt * 8 + (lane & 3) * 2;
        float b0 = bias_s[c0], b1 = bias_s[c0 + 1];
        float v0 = acc[nt][0] + b0, v1 = acc[nt][1] + b1;
        float v2 = acc[nt][2] + b0, v3 = acc[nt][3] + b1;
        __half2 h0 = __floats2half2_rn(v0, v1);
        __half2 h1 = __floats2half2_rn(v2, v3);
        float2 f0 = __half22float2(h0);
        float2 f1 = __half22float2(h1);
        size_t o0 = (size_t)(b * 1024 + r0) * C_DIM + oh * 128 + c0;
        size_t o1 = (size_t)(b * 1024 + r0 + 8) * C_DIM + oh * 128 + c0;
        *(__half2*)&Yh[o0] = h0;
        *(__half2*)&Yh[o1] = h1;
        *(__half2*)&Yl[o0] = __floats2half2_rn(v0 - f0.x, v1 - f0.y);
        *(__half2*)&Yl[o1] = __floats2half2_rn(v2 - f1.x, v3 - f1.y);
    }
}

// ------------------- flash attention (byte-identical to R14 win) -------------------
__global__ void __launch_bounds__(256, 2)
attn_mma_kernel()
{
    __shared__ __align__(16) __half pool[20480];

    const int tid = threadIdx.x, lane = tid & 31, w = tid >> 5;
    const int qt = blockIdx.x, n = blockIdx.y, b = blockIdx.z;
    const int rr = lane & 15;
    const int hoff = (lane & 16) ? 8 : 0;
    const int knr = (lane & 7) + ((lane >> 4) << 3);
    const int knc = ((lane >> 3) & 1) * 8;
    const int kvrow = tid >> 2, kvseg = tid & 3;

    {
        __half* base = pool + 10240;
        size_t g = ((size_t)(b * 1024 + kvrow)) * C_DIM + n * 32 + kvseg * 8;
        uint32_t s = smem_u32(base + kvrow * 40 + kvseg * 8);
        cpa16(s, &g_kth[g]);
        cpa16(s + 2560 * 2, &g_ktl[g]);
        cpa16(s + 5120 * 2, &g_vth[g]);
        cpa16(s + 7680 * 2, &g_vtl[g]);
        CP_COMMIT();
    }

    for (int u = tid; u < 512; u += 256) {
        int row = u >> 2, seg = u & 3;
        size_t g = ((size_t)(b * 1024 + qt * 128 + row)) * C_DIM + n * 32 + seg * 8;
        *(uint4*)&pool[row * 40 + seg * 8] = *(const uint4*)&g_qh[g];
    }
    __syncthreads();

    uint32_t qf[2][4];
    #pragma unroll
    for (int kc = 0; kc < 2; kc++)
        ldsm_x4(qf[kc], smem_u32(&pool[(w * 16 + rr) * 40 + kc * 16 + hoff]));
    __syncthreads();

    float oacc[4][4] = {};
    float l0 = 0.0f, l1 = 0.0f;

    for (int t = 0; t < 16; t++) {
        CP_WAIT0();
        __syncthreads();

        if (t < 15) {
            __half* base = pool + (((t + 1) & 1) ? 0 : 10240);
            size_t g = ((size_t)(b * 1024 + (t + 1) * 64 + kvrow)) * C_DIM + n * 32 + kvseg * 8;
            uint32_t s = smem_u32(base + kvrow * 40 + kvseg * 8);
            cpa16(s, &g_kth[g]);
            cpa16(s + 2560 * 2, &g_ktl[g]);
            cpa16(s + 5120 * 2, &g_vth[g]);
            cpa16(s + 7680 * 2, &g_vtl[g]);
            CP_COMMIT();
        }

        __half* cur = pool + ((t & 1) ? 0 : 10240);
        __half* ksh0 = cur;
        __half* ksh1 = cur + 2560;
        __half* vsh0 = cur + 5120;
        __half* vsh1 = cur + 7680;

        float sacc[8][4];
        #pragma unroll
        for (int ntp = 0; ntp < 4; ntp++) {
            float* s0 = sacc[2 * ntp];
            float* s1 = sacc[2 * ntp + 1];
            s0[0] = s0[1] = s0[2] = s0[3] = 0.0f;
            s1[0] = s1[1] = s1[2] = s1[3] = 0.0f;
            #pragma unroll
            for (int kc = 0; kc < 2; kc++) {
                uint32_t off = (ntp * 16 + knr) * 40 + kc * 16 + knc;
                uint32_t kbh[4], kbl[4];
                ldsm_x4(kbh, smem_u32(&ksh0[off]));
                ldsm_x4(kbl, smem_u32(&ksh1[off]));
                mma16816(s0, qf[kc], kbh);
                mma16816(s1, qf[kc], kbh + 2);
                mma16816(s0, qf[kc], kbl);
                mma16816(s1, qf[kc], kbl + 2);
            }
        }

        float rs0 = 0.0f, rs1 = 0.0f;
        #pragma unroll
        for (int nt = 0; nt < 8; nt++) {
            sacc[nt][0] = ex2f(sacc[nt][0]);
            sacc[nt][1] = ex2f(sacc[nt][1]);
            sacc[nt][2] = ex2f(sacc[nt][2]);
            sacc[nt][3] = ex2f(sacc[nt][3]);
            rs0 += sacc[nt][0] + sacc[nt][1];
            rs1 += sacc[nt][2] + sacc[nt][3];
        }
        rs0 += shflx(rs0, 1); rs0 += shflx(rs0, 2);
        rs1 += shflx(rs1, 1); rs1 += shflx(rs1, 2);
        l0 += rs0; l1 += rs1;

        uint32_t pfh[4][4];
        #pragma unroll
        for (int kc = 0; kc < 4; kc++) {
            const float* s0 = sacc[2 * kc];
            const float* s1 = sacc[2 * kc + 1];
            pfh[kc][0] = pack_h2(s0[0], s0[1]);
            pfh[kc][1] = pack_h2(s0[2], s0[3]);
            pfh[kc][2] = pack_h2(s1[0], s1[1]);
            pfh[kc][3] = pack_h2(s1[2], s1[3]);
        }

        #pragma unroll
        for (int kc = 0; kc < 4; kc++) {
            #pragma unroll
            for (int np = 0; np < 2; np++) {
                uint32_t vbh[4], vbl[4];
                uint32_t off = (kc * 16 + rr) * 40 + np * 16 + hoff;
                ldsm_x4t(vbh, smem_u32(&vsh0[off]));
                ldsm_x4t(vbl, smem_u32(&vsh1[off]));
                mma16816(oacc[2 * np],     pfh[kc], vbh);
                mma16816(oacc[2 * np + 1], pfh[kc], vbh + 2);
                mma16816(oacc[2 * np],     pfh[kc], vbl);
                mma16816(oacc[2 * np + 1], pfh[kc], vbl + 2);
            }
        }
    }

    float i0 = 1.0f / l0, i1 = 1.0f / l1;
    int q0 = qt * 128 + w * 16 + (lane >> 2);
    #pragma unroll
    for (int nt = 0; nt < 4; nt++) {
        int c = n * 32 + nt * 8 + (lane & 3) * 2;
        float v00 = oacc[nt][0] * i0, v01 = oacc[nt][1] * i0;
        float v10 = oacc[nt][2] * i1, v11 = oacc[nt][3] * i1;
        size_t b0 = ((size_t)(b * 256 + c)) * L_DIM + q0;
        size_t b1 = b0 + L_DIM;
        __half h;
        h = __float2half_rn(v00); g_xth[b0] = h;     g_xtl[b0] = __float2half_rn(v00 - __half2float(h));
        h = __float2half_rn(v01); g_xth[b1] = h;     g_xtl[b1] = __float2half_rn(v01 - __half2float(h));
        h = __float2half_rn(v10); g_xth[b0 + 8] = h; g_xtl[b0 + 8] = __float2half_rn(v10 - __half2float(h));
        h = __float2half_rn(v11); g_xth[b1 + 8] = h; g_xtl[b1 + 8] = __float2half_rn(v11 - __half2float(h));
    }
}

// ------------------- mma output projection (byte-identical to R14 win) -------------------
__global__ void __launch_bounds__(256)
proj_o_mma_kernel(const float* __restrict__ bo, float* __restrict__ out)
{
    extern __shared__ __half dynsm[];
    __shared__ float bias_s[128];

    const int tid = threadIdx.x, lane = tid & 31, w = tid >> 5;
    const int lt = blockIdx.x >> 1, oh = blockIdx.x & 1;
    const int b = blockIdx.z;

    if (tid < 128) bias_s[tid] = bo[oh * 128 + tid];

    const int arow = tid >> 2, aseg = tid & 3;
    const int brow = tid >> 4, bseg = tid & 15;

    {
        __half* base = dynsm;
        #pragma unroll
        for (int i = 0; i < 2; i++) {
            int row = arow + i * 64;
            int g = (oh * 128 + row) * C_DIM + aseg * 8;
            cpa16(smem_u32(base + row * 40 + aseg * 8), &g_woh[g]);
        }
        #pragma unroll
        for (int i = 0; i < 2; i++) {
            int row = brow + i * 16;
            size_t g = ((size_t)(b * 256 + row)) * L_DIM + lt * 128 + bseg * 8;
            cpa16(smem_u32(base + 5120 + row * 136 + bseg * 8), &g_xth[g]);
            cpa16(smem_u32(base + 9472 + row * 136 + bseg * 8), &g_xtl[g]);
        }
        CP_COMMIT();
    }

    float acc[16][4] = {};
    const int rr = lane & 15;
    const int chi = (lane & 16) ? 8 : 0;

    for (int it = 0; it < 8; it++) {
        CP_WAIT0();
        __syncthreads();

        if (it < 7) {
            __half* base = dynsm + ((it + 1) & 1) * PO_STAGE;
            int kc0 = (it + 1) * 32;
            #pragma unroll
            for (int i = 0; i < 2; i++) {
                int row = arow + i * 64;
                int g = (oh * 128 + row) * C_DIM + kc0 + aseg * 8;
                cpa16(smem_u32(base + row * 40 + aseg * 8), &g_woh[g]);
            }
            #pragma unroll
            for (int i = 0; i < 2; i++) {
                int row = brow + i * 16;
                size_t g = ((size_t)(b * 256 + kc0 + row)) * L_DIM + lt * 128 + bseg * 8;
                cpa16(smem_u32(base + 5120 + row * 136 + bseg * 8), &g_xth[g]);
                cpa16(smem_u32(base + 9472 + row * 136 + bseg * 8), &g_xtl[g]);
            }
            CP_COMMIT();
        }

        __half* cur = dynsm + (it & 1) * PO_STAGE;
        __half* ah = cur;
        __half* bh_s = cur + 5120;
        __half* bl_s = cur + 9472;

        uint32_t af[2][4];
        #pragma unroll
        for (int kc = 0; kc < 2; kc++)
            ldsm_x4(af[kc], smem_u32(&ah[(w * 16 + rr) * 40 + kc * 16 + chi]));

        #pragma unroll
        for (int nt = 0; nt < 16; nt += 2) {
            #pragma unroll
            for (int kc = 0; kc < 2; kc++) {
                uint32_t bh[4], bl[4];
                ldsm_x4t(bh, smem_u32(&bh_s[(kc * 16 + rr) * 136 + nt * 8 + chi]));
                ldsm_x4t(bl, smem_u32(&bl_s[(kc * 16 + rr) * 136 + nt * 8 + chi]));
                mma16816(acc[nt],     af[kc], bh);
                mma16816(acc[nt + 1], af[kc], bh + 2);
                mma16816(acc[nt],     af[kc], bl);
                mma16816(acc[nt + 1], af[kc], bl + 2);
            }
        }
    }

    const int orow = oh * 128 + w * 16 + (lane >> 2);
    const float bb0 = bias_s[w * 16 + (lane >> 2)];
    const float bb1 = bias_s[w * 16 + (lane >> 2) + 8];
    #pragma unroll
    for (int nt = 0; nt < 16; nt++) {
        int lcol = lt * 128 + nt * 8 + (lane & 3) * 2;
        float2 y0, y1;
        y0.x = acc[nt][0] + bb0; y0.y = acc[nt][1] + bb0;
        y1.x = acc[nt][2] + bb1; y1.y = acc[nt][3] + bb1;
        *(float2*)&out[((size_t)(b * 256 + orow)) * L_DIM + lcol] = y0;
        *(float2*)&out[((size_t)(b * 256 + orow + 8)) * L_DIM + lcol] = y1;
    }
}

// ---------------------------------------------------------------------------
extern "C" void kernel_launch(void* const* d_in, const int* in_sizes, int n_in,
                              void* d_out, int out_size)
{
    const float* x  = (const float*)d_in[0];
    const float* wq = (const float*)d_in[1];
    const float* bq = (const float*)d_in[2];
    const float* wk = (const float*)d_in[3];
    const float* bk = (const float*)d_in[4];
    const float* wv = (const float*)d_in[5];
    const float* bv = (const float*)d_in[6];
    const float* wo = (const float*)d_in[7];
    const float* bo = (const float*)d_in[8];
    float* out = (float*)d_out;

    cudaFuncSetAttribute(proj_q_mma_kernel, cudaFuncAttributeMaxDynamicSharedMemorySize, PQ_BYTES);
    cudaFuncSetAttribute(proj_kv_mma_kernel, cudaFuncAttributeMaxDynamicSharedMemorySize, PJ_BYTES);
    cudaFuncSetAttribute(proj_o_mma_kernel, cudaFuncAttributeMaxDynamicSharedMemorySize, PO_BYTES);

    split_w_kernel<<<dim3(8, 8, 3), dim3(32, 8)>>>(wq, wk, wv);
    split_wo_kernel<<<128, 256>>>(wo);
    convert_x_kernel<<<dim3(32, 8, 16), dim3(32, 8)>>>(x);
    proj_kv_mma_kernel<<<dim3(16, 2, 16), 256, PJ_BYTES>>>(bk, bv);
    proj_q_mma_kernel<<<dim3(16, 1, 16), 256, PQ_BYTES>>>(bq);
    attn_mma_kernel<<<dim3(8, 8, 16), 256>>>();
    proj_o_mma_kernel<<<dim3(16, 1, 16), 256, PO_BYTES>>>(bo, out);
}

// round 16
// speedup vs baseline: 1.3382x; 1.1194x over previous
#include <cuda_runtime.h>
#include <cuda_fp16.h>
#include <cstdint>

#define C_DIM 256
#define L_DIM 1024
#define B_DIM 16
#define NH 8
#define DH 32
#define SCALE 0.17677669529663687f
#define LOG2E 1.4426950408889634f

// f16 hi/lo split buffers
__device__ __half g_qh[B_DIM * L_DIM * C_DIM];   // [b][l][c]
__device__ __half g_kth[B_DIM * L_DIM * C_DIM];  // k [b][l][c]
__device__ __half g_ktl[B_DIM * L_DIM * C_DIM];
__device__ __half g_vth[B_DIM * L_DIM * C_DIM];  // v [b][l][c]
__device__ __half g_vtl[B_DIM * L_DIM * C_DIM];  // (unused by attn now; kv kernel still writes)
__device__ __half g_xth[B_DIM * L_DIM * C_DIM];  // x^T split; reused as att hi [b][c][l]
__device__ __half g_xtl[B_DIM * L_DIM * C_DIM];
__device__ __half g_wh[3 * C_DIM * C_DIM];       // W^T [sel][c][o]
__device__ __half g_wl[3 * C_DIM * C_DIM];
__device__ __half g_woh[C_DIM * C_DIM];          // Wo [o][c]

__device__ __forceinline__ float ex2f(float x) {
    float r; asm("ex2.approx.f32 %0, %1;" : "=f"(r) : "f"(x)); return r;
}
__device__ __forceinline__ uint32_t smem_u32(const void* p) {
    uint32_t a;
    asm("{ .reg .u64 t; cvta.to.shared.u64 t, %1; cvt.u32.u64 %0, t; }" : "=r"(a) : "l"(p));
    return a;
}
__device__ __forceinline__ uint32_t pack_h2(float lo, float hi) {
    uint32_t r; asm("cvt.rn.f16x2.f32 %0, %1, %2;" : "=r"(r) : "f"(hi), "f"(lo)); return r;
}
__device__ __forceinline__ void ldsm_x4(uint32_t* r, uint32_t a) {
    asm volatile("ldmatrix.sync.aligned.m8n8.x4.shared.b16 {%0,%1,%2,%3}, [%4];"
        : "=r"(r[0]), "=r"(r[1]), "=r"(r[2]), "=r"(r[3]) : "r"(a));
}
__device__ __forceinline__ void ldsm_x4t(uint32_t* r, uint32_t a) {
    asm volatile("ldmatrix.sync.aligned.m8n8.x4.trans.shared.b16 {%0,%1,%2,%3}, [%4];"
        : "=r"(r[0]), "=r"(r[1]), "=r"(r[2]), "=r"(r[3]) : "r"(a));
}
__device__ __forceinline__ void mma16816(float* d, const uint32_t* a, const uint32_t* b) {
    asm volatile("mma.sync.aligned.m16n8k16.row.col.f32.f16.f16.f32 "
        "{%0,%1,%2,%3}, {%4,%5,%6,%7}, {%8,%9}, {%0,%1,%2,%3};"
        : "+f"(d[0]), "+f"(d[1]), "+f"(d[2]), "+f"(d[3])
        : "r"(a[0]), "r"(a[1]), "r"(a[2]), "r"(a[3]), "r"(b[0]), "r"(b[1]));
}
__device__ __forceinline__ float shflx(float v, int m) {
    return __shfl_xor_sync(0xffffffffu, v, m);
}
__device__ __forceinline__ void cpa16(uint32_t s, const void* g) {
    asm volatile("cp.async.cg.shared.global [%0], [%1], 16;" :: "r"(s), "l"(g));
}
#define CP_COMMIT() asm volatile("cp.async.commit_group;" ::: "memory")
#define CP_WAIT0()  asm volatile("cp.async.wait_group 0;" ::: "memory")

// ------------------- prep kernels -------------------
__global__ void __launch_bounds__(256)
split_w_kernel(const float* __restrict__ wq, const float* __restrict__ wk, const float* __restrict__ wv)
{
    __shared__ float t[32][33];
    const int sel = blockIdx.z;
    const float* W = (sel == 0) ? wq : (sel == 1) ? wk : wv;
    __half* dh = g_wh + sel * C_DIM * C_DIM;
    __half* dl = g_wl + sel * C_DIM * C_DIM;
    const int o0 = blockIdx.x * 32, c0 = blockIdx.y * 32;
    const int tx = threadIdx.x, ty = threadIdx.y;
    #pragma unroll
    for (int i = 0; i < 4; i++)
        t[ty + 8 * i][tx] = W[(o0 + ty + 8 * i) * C_DIM + c0 + tx];
    __syncthreads();
    #pragma unroll
    for (int i = 0; i < 4; i++) {
        float v = t[tx][ty + 8 * i];
        __half h = __float2half_rn(v);
        int o = (c0 + ty + 8 * i) * C_DIM + o0 + tx;
        dh[o] = h;
        dl[o] = __float2half_rn(v - __half2float(h));
    }
}

__global__ void __launch_bounds__(256)
split_wo_kernel(const float* __restrict__ wo)
{
    int i = blockIdx.x * 256 + threadIdx.x;
    const float2 v = ((const float2*)wo)[i];
    ((__half2*)g_woh)[i] = __floats2half2_rn(v.x, v.y);
}

__global__ void __launch_bounds__(256)
convert_x_kernel(const float* __restrict__ x)
{
    __shared__ float t[32][33];
    const int b = blockIdx.z;
    const float* src = x + (size_t)b * C_DIM * L_DIM;
    __half* dh = g_xth + (size_t)b * L_DIM * C_DIM;
    __half* dl = g_xtl + (size_t)b * L_DIM * C_DIM;
    const int l0 = blockIdx.x * 32, c0 = blockIdx.y * 32;
    const int tx = threadIdx.x, ty = threadIdx.y;
    #pragma unroll
    for (int i = 0; i < 4; i++)
        t[ty + 8 * i][tx] = src[(size_t)(c0 + ty + 8 * i) * L_DIM + l0 + tx];
    __syncthreads();
    #pragma unroll
    for (int i = 0; i < 4; i++) {
        float v = t[tx][ty + 8 * i];
        __half h = __float2half_rn(v);
        size_t o = (size_t)(l0 + ty + 8 * i) * C_DIM + c0 + tx;
        dh[o] = h;
        dl[o] = __float2half_rn(v - __half2float(h));
    }
}

// ------------------- shared projection constants -------------------
#define PJ_STAGE 18944
#define PJ_BYTES (2 * PJ_STAGE * 2)
#define PQ_STAGE 14592
#define PQ_BYTES (2 * PQ_STAGE * 2)
// proj_o stage: AH 0 (5120), BH 5120 (4352); stage = 9472
#define PO_STAGE 9472
#define PO_BYTES (2 * PO_STAGE * 2)

// ------------------- q projection: 2-term (unchanged from R15) -------------------
__global__ void __launch_bounds__(256, 2)
proj_q_mma_kernel(const float* __restrict__ bq)
{
    extern __shared__ __half dynsm[];
    __shared__ float bias_s[128];

    const int tid = threadIdx.x, lane = tid & 31, w = tid >> 5;
    const int lt = blockIdx.x >> 1, oh = blockIdx.x & 1;
    const int b = blockIdx.z;

    const __half* xh = g_xth + (size_t)b * L_DIM * C_DIM;
    const __half* xl = g_xtl + (size_t)b * L_DIM * C_DIM;
    const __half* wh = g_wh;

    if (tid < 128) bias_s[tid] = bq[oh * 128 + tid];

    const int arow = tid >> 2, aseg = tid & 3;
    const int brow = tid >> 4, bseg = tid & 15;

    {
        __half* base = dynsm;
        #pragma unroll
        for (int i = 0; i < 2; i++) {
            int row = arow + i * 64;
            size_t g = (size_t)(lt * 128 + row) * C_DIM + aseg * 8;
            cpa16(smem_u32(base + row * 40 + aseg * 8), &xh[g]);
            cpa16(smem_u32(base + 5120 + row * 40 + aseg * 8), &xl[g]);
        }
        #pragma unroll
        for (int i = 0; i < 2; i++) {
            int row = brow + i * 16;
            cpa16(smem_u32(base + 10240 + row * 136 + bseg * 8), &wh[row * C_DIM + oh * 128 + bseg * 8]);
        }
        CP_COMMIT();
    }

    float acc[16][4] = {};
    const int rr = lane & 15;
    const int chi = (lane & 16) ? 8 : 0;

    for (int it = 0; it < 8; it++) {
        CP_WAIT0();
        __syncthreads();

        if (it < 7) {
            __half* base = dynsm + ((it + 1) & 1) * PQ_STAGE;
            int kc0 = (it + 1) * 32;
            #pragma unroll
            for (int i = 0; i < 2; i++) {
                int row = arow + i * 64;
                size_t g = (size_t)(lt * 128 + row) * C_DIM + kc0 + aseg * 8;
                cpa16(smem_u32(base + row * 40 + aseg * 8), &xh[g]);
                cpa16(smem_u32(base + 5120 + row * 40 + aseg * 8), &xl[g]);
            }
            #pragma unroll
            for (int i = 0; i < 2; i++) {
                int row = brow + i * 16;
                cpa16(smem_u32(base + 10240 + row * 136 + bseg * 8), &wh[(kc0 + row) * C_DIM + oh * 128 + bseg * 8]);
            }
            CP_COMMIT();
        }

        __half* cur = dynsm + (it & 1) * PQ_STAGE;
        __half* ah = cur;
        __half* al = cur + 5120;
        __half* bh_s = cur + 10240;

        uint32_t af[2][2][4];
        #pragma unroll
        for (int kc = 0; kc < 2; kc++) {
            ldsm_x4(af[0][kc], smem_u32(&ah[(w * 16 + rr) * 40 + kc * 16 + chi]));
            ldsm_x4(af[1][kc], smem_u32(&al[(w * 16 + rr) * 40 + kc * 16 + chi]));
        }

        #pragma unroll
        for (int nt = 0; nt < 16; nt += 2) {
            #pragma unroll
            for (int kc = 0; kc < 2; kc++) {
                uint32_t bh[4];
                ldsm_x4t(bh, smem_u32(&bh_s[(kc * 16 + rr) * 136 + nt * 8 + chi]));
                mma16816(acc[nt],     af[0][kc], bh);
                mma16816(acc[nt + 1], af[0][kc], bh + 2);
                mma16816(acc[nt],     af[1][kc], bh);
                mma16816(acc[nt + 1], af[1][kc], bh + 2);
            }
        }
    }

    const int r0 = lt * 128 + w * 16 + (lane >> 2);
    #pragma unroll
    for (int nt = 0; nt < 16; nt++) {
        int c0 = nt * 8 + (lane & 3) * 2;
        float b0 = bias_s[c0], b1 = bias_s[c0 + 1];
        float v0 = (acc[nt][0] + b0) * (SCALE * LOG2E), v1 = (acc[nt][1] + b1) * (SCALE * LOG2E);
        float v2 = (acc[nt][2] + b0) * (SCALE * LOG2E), v3 = (acc[nt][3] + b1) * (SCALE * LOG2E);
        size_t o0 = (size_t)(b * 1024 + r0) * C_DIM + oh * 128 + c0;
        size_t o1 = (size_t)(b * 1024 + r0 + 8) * C_DIM + oh * 128 + c0;
        *(__half2*)&g_qh[o0] = __floats2half2_rn(v0, v1);
        *(__half2*)&g_qh[o1] = __floats2half2_rn(v2, v3);
    }
}

// ------------------- k/v projection: 3-term (unchanged from R15) -------------------
__global__ void __launch_bounds__(256, 2)
proj_kv_mma_kernel(const float* __restrict__ bk, const float* __restrict__ bv)
{
    extern __shared__ __half dynsm[];
    __shared__ float bias_s[128];

    const int tid = threadIdx.x, lane = tid & 31, w = tid >> 5;
    const int lt = blockIdx.x >> 1, oh = blockIdx.x & 1;
    const int sel = blockIdx.y + 1, b = blockIdx.z;   // 1 = k, 2 = v

    const __half* xh = g_xth + (size_t)b * L_DIM * C_DIM;
    const __half* xl = g_xtl + (size_t)b * L_DIM * C_DIM;
    const __half* wh = g_wh + sel * C_DIM * C_DIM;
    const __half* wl = g_wl + sel * C_DIM * C_DIM;
    const float* bias = (sel == 1) ? bk : bv;
    __half* Yh = (sel == 1) ? g_kth : g_vth;
    __half* Yl = (sel == 1) ? g_ktl : g_vtl;

    if (tid < 128) bias_s[tid] = bias[oh * 128 + tid];

    const int arow = tid >> 2, aseg = tid & 3;
    const int brow = tid >> 4, bseg = tid & 15;

    {
        __half* base = dynsm;
        #pragma unroll
        for (int i = 0; i < 2; i++) {
            int row = arow + i * 64;
            size_t g = (size_t)(lt * 128 + row) * C_DIM + aseg * 8;
            cpa16(smem_u32(base + row * 40 + aseg * 8), &xh[g]);
            cpa16(smem_u32(base + 5120 + row * 40 + aseg * 8), &xl[g]);
        }
        #pragma unroll
        for (int i = 0; i < 2; i++) {
            int row = brow + i * 16;
            int g = row * C_DIM + oh * 128 + bseg * 8;
            cpa16(smem_u32(base + 10240 + row * 136 + bseg * 8), &wh[g]);
            cpa16(smem_u32(base + 14592 + row * 136 + bseg * 8), &wl[g]);
        }
        CP_COMMIT();
    }

    float acc[16][4] = {};
    const int rr = lane & 15;
    const int chi = (lane & 16) ? 8 : 0;

    for (int it = 0; it < 8; it++) {
        CP_WAIT0();
        __syncthreads();

        if (it < 7) {
            __half* base = dynsm + ((it + 1) & 1) * PJ_STAGE;
            int kc0 = (it + 1) * 32;
            #pragma unroll
            for (int i = 0; i < 2; i++) {
                int row = arow + i * 64;
                size_t g = (size_t)(lt * 128 + row) * C_DIM + kc0 + aseg * 8;
                cpa16(smem_u32(base + row * 40 + aseg * 8), &xh[g]);
                cpa16(smem_u32(base + 5120 + row * 40 + aseg * 8), &xl[g]);
            }
            #pragma unroll
            for (int i = 0; i < 2; i++) {
                int row = brow + i * 16;
                int g = (kc0 + row) * C_DIM + oh * 128 + bseg * 8;
                cpa16(smem_u32(base + 10240 + row * 136 + bseg * 8), &wh[g]);
                cpa16(smem_u32(base + 14592 + row * 136 + bseg * 8), &wl[g]);
            }
            CP_COMMIT();
        }

        __half* cur = dynsm + (it & 1) * PJ_STAGE;
        __half* ah = cur;
        __half* al = cur + 5120;
        __half* bh_s = cur + 10240;
        __half* bl_s = cur + 14592;

        uint32_t af[2][2][4];
        #pragma unroll
        for (int kc = 0; kc < 2; kc++) {
            ldsm_x4(af[0][kc], smem_u32(&ah[(w * 16 + rr) * 40 + kc * 16 + chi]));
            ldsm_x4(af[1][kc], smem_u32(&al[(w * 16 + rr) * 40 + kc * 16 + chi]));
        }

        #pragma unroll
        for (int nt = 0; nt < 16; nt += 2) {
            #pragma unroll
            for (int kc = 0; kc < 2; kc++) {
                uint32_t bh[4], bl[4];
                ldsm_x4t(bh, smem_u32(&bh_s[(kc * 16 + rr) * 136 + nt * 8 + chi]));
                ldsm_x4t(bl, smem_u32(&bl_s[(kc * 16 + rr) * 136 + nt * 8 + chi]));
                mma16816(acc[nt],     af[0][kc], bh);
                mma16816(acc[nt + 1], af[0][kc], bh + 2);
                mma16816(acc[nt],     af[0][kc], bl);
                mma16816(acc[nt + 1], af[0][kc], bl + 2);
                mma16816(acc[nt],     af[1][kc], bh);
                mma16816(acc[nt + 1], af[1][kc], bh + 2);
            }
        }
    }

    const int r0 = lt * 128 + w * 16 + (lane >> 2);
    #pragma unroll
    for (int nt = 0; nt < 16; nt++) {
        int c0 = nt * 8 + (lane & 3) * 2;
        float b0 = bias_s[c0], b1 = bias_s[c0 + 1];
        float v0 = acc[nt][0] + b0, v1 = acc[nt][1] + b1;
        float v2 = acc[nt][2] + b0, v3 = acc[nt][3] + b1;
        __half2 h0 = __floats2half2_rn(v0, v1);
        __half2 h1 = __floats2half2_rn(v2, v3);
        float2 f0 = __half22float2(h0);
        float2 f1 = __half22float2(h1);
        size_t o0 = (size_t)(b * 1024 + r0) * C_DIM + oh * 128 + c0;
        size_t o1 = (size_t)(b * 1024 + r0 + 8) * C_DIM + oh * 128 + c0;
        *(__half2*)&Yh[o0] = h0;
        *(__half2*)&Yh[o1] = h1;
        *(__half2*)&Yl[o0] = __floats2half2_rn(v0 - f0.x, v1 - f0.y);
        *(__half2*)&Yl[o1] = __floats2half2_rn(v2 - f1.x, v3 - f1.y);
    }
}

// ------------------- flash attention: O = Ph*Vh only (V hi-only) -------------------
// pool (halves): Q hi [0, 5120) (overlaid by buf1); buf1 = [0, 7680); buf0 = [7680, 15360)
// buffer layout: Kh +0, Kl +2560, Vh +5120 (each 64 rows x pitch 40)
__global__ void __launch_bounds__(256, 2)
attn_mma_kernel()
{
    __shared__ __align__(16) __half pool[15360];

    const int tid = threadIdx.x, lane = tid & 31, w = tid >> 5;
    const int qt = blockIdx.x, n = blockIdx.y, b = blockIdx.z;
    const int rr = lane & 15;
    const int hoff = (lane & 16) ? 8 : 0;
    const int knr = (lane & 7) + ((lane >> 4) << 3);
    const int knc = ((lane >> 3) & 1) * 8;
    const int kvrow = tid >> 2, kvseg = tid & 3;

    {
        __half* base = pool + 7680;
        size_t g = ((size_t)(b * 1024 + kvrow)) * C_DIM + n * 32 + kvseg * 8;
        uint32_t s = smem_u32(base + kvrow * 40 + kvseg * 8);
        cpa16(s, &g_kth[g]);
        cpa16(s + 2560 * 2, &g_ktl[g]);
        cpa16(s + 5120 * 2, &g_vth[g]);
        CP_COMMIT();
    }

    for (int u = tid; u < 512; u += 256) {
        int row = u >> 2, seg = u & 3;
        size_t g = ((size_t)(b * 1024 + qt * 128 + row)) * C_DIM + n * 32 + seg * 8;
        *(uint4*)&pool[row * 40 + seg * 8] = *(const uint4*)&g_qh[g];
    }
    __syncthreads();

    uint32_t qf[2][4];
    #pragma unroll
    for (int kc = 0; kc < 2; kc++)
        ldsm_x4(qf[kc], smem_u32(&pool[(w * 16 + rr) * 40 + kc * 16 + hoff]));
    __syncthreads();

    float oacc[4][4] = {};
    float l0 = 0.0f, l1 = 0.0f;

    for (int t = 0; t < 16; t++) {
        CP_WAIT0();
        __syncthreads();

        if (t < 15) {
            __half* base = pool + (((t + 1) & 1) ? 0 : 7680);
            size_t g = ((size_t)(b * 1024 + (t + 1) * 64 + kvrow)) * C_DIM + n * 32 + kvseg * 8;
            uint32_t s = smem_u32(base + kvrow * 40 + kvseg * 8);
            cpa16(s, &g_kth[g]);
            cpa16(s + 2560 * 2, &g_ktl[g]);
            cpa16(s + 5120 * 2, &g_vth[g]);
            CP_COMMIT();
        }

        __half* cur = pool + ((t & 1) ? 0 : 7680);
        __half* ksh0 = cur;
        __half* ksh1 = cur + 2560;
        __half* vsh0 = cur + 5120;

        // ---- S = QhKh + QhKl ----
        float sacc[8][4];
        #pragma unroll
        for (int ntp = 0; ntp < 4; ntp++) {
            float* s0 = sacc[2 * ntp];
            float* s1 = sacc[2 * ntp + 1];
            s0[0] = s0[1] = s0[2] = s0[3] = 0.0f;
            s1[0] = s1[1] = s1[2] = s1[3] = 0.0f;
            #pragma unroll
            for (int kc = 0; kc < 2; kc++) {
                uint32_t off = (ntp * 16 + knr) * 40 + kc * 16 + knc;
                uint32_t kbh[4], kbl[4];
                ldsm_x4(kbh, smem_u32(&ksh0[off]));
                ldsm_x4(kbl, smem_u32(&ksh1[off]));
                mma16816(s0, qf[kc], kbh);
                mma16816(s1, qf[kc], kbh + 2);
                mma16816(s0, qf[kc], kbl);
                mma16816(s1, qf[kc], kbl + 2);
            }
        }

        // ---- softmax without max-subtraction ----
        float rs0 = 0.0f, rs1 = 0.0f;
        #pragma unroll
        for (int nt = 0; nt < 8; nt++) {
            sacc[nt][0] = ex2f(sacc[nt][0]);
            sacc[nt][1] = ex2f(sacc[nt][1]);
            sacc[nt][2] = ex2f(sacc[nt][2]);
            sacc[nt][3] = ex2f(sacc[nt][3]);
            rs0 += sacc[nt][0] + sacc[nt][1];
            rs1 += sacc[nt][2] + sacc[nt][3];
        }
        rs0 += shflx(rs0, 1); rs0 += shflx(rs0, 2);
        rs1 += shflx(rs1, 1); rs1 += shflx(rs1, 2);
        l0 += rs0; l1 += rs1;

        uint32_t pfh[4][4];
        #pragma unroll
        for (int kc = 0; kc < 4; kc++) {
            const float* s0 = sacc[2 * kc];
            const float* s1 = sacc[2 * kc + 1];
            pfh[kc][0] = pack_h2(s0[0], s0[1]);
            pfh[kc][1] = pack_h2(s0[2], s0[3]);
            pfh[kc][2] = pack_h2(s1[0], s1[1]);
            pfh[kc][3] = pack_h2(s1[2], s1[3]);
        }

        // ---- O += Ph*Vh ----
        #pragma unroll
        for (int kc = 0; kc < 4; kc++) {
            #pragma unroll
            for (int np = 0; np < 2; np++) {
                uint32_t vbh[4];
                uint32_t off = (kc * 16 + rr) * 40 + np * 16 + hoff;
                ldsm_x4t(vbh, smem_u32(&vsh0[off]));
                mma16816(oacc[2 * np],     pfh[kc], vbh);
                mma16816(oacc[2 * np + 1], pfh[kc], vbh + 2);
            }
        }
    }

    // ---- epilogue: O hi-only [b][c][l] ----
    float i0 = 1.0f / l0, i1 = 1.0f / l1;
    int q0 = qt * 128 + w * 16 + (lane >> 2);
    #pragma unroll
    for (int nt = 0; nt < 4; nt++) {
        int c = n * 32 + nt * 8 + (lane & 3) * 2;
        size_t b0 = ((size_t)(b * 256 + c)) * L_DIM + q0;
        size_t b1 = b0 + L_DIM;
        g_xth[b0] = __float2half_rn(oacc[nt][0] * i0);
        g_xth[b1] = __float2half_rn(oacc[nt][1] * i0);
        g_xth[b0 + 8] = __float2half_rn(oacc[nt][2] * i1);
        g_xth[b1 + 8] = __float2half_rn(oacc[nt][3] * i1);
    }
}

// ------------------- mma output projection: plain f16 (Woh x att-hi) -------------------
__global__ void __launch_bounds__(256)
proj_o_mma_kernel(const float* __restrict__ bo, float* __restrict__ out)
{
    extern __shared__ __half dynsm[];
    __shared__ float bias_s[128];

    const int tid = threadIdx.x, lane = tid & 31, w = tid >> 5;
    const int lt = blockIdx.x >> 1, oh = blockIdx.x & 1;
    const int b = blockIdx.z;

    if (tid < 128) bias_s[tid] = bo[oh * 128 + tid];

    const int arow = tid >> 2, aseg = tid & 3;
    const int brow = tid >> 4, bseg = tid & 15;

    {
        __half* base = dynsm;
        #pragma unroll
        for (int i = 0; i < 2; i++) {
            int row = arow + i * 64;
            cpa16(smem_u32(base + row * 40 + aseg * 8), &g_woh[(oh * 128 + row) * C_DIM + aseg * 8]);
        }
        #pragma unroll
        for (int i = 0; i < 2; i++) {
            int row = brow + i * 16;
            size_t g = ((size_t)(b * 256 + row)) * L_DIM + lt * 128 + bseg * 8;
            cpa16(smem_u32(base + 5120 + row * 136 + bseg * 8), &g_xth[g]);
        }
        CP_COMMIT();
    }

    float acc[16][4] = {};
    const int rr = lane & 15;
    const int chi = (lane & 16) ? 8 : 0;

    for (int it = 0; it < 8; it++) {
        CP_WAIT0();
        __syncthreads();

        if (it < 7) {
            __half* base = dynsm + ((it + 1) & 1) * PO_STAGE;
            int kc0 = (it + 1) * 32;
            #pragma unroll
            for (int i = 0; i < 2; i++) {
                int row = arow + i * 64;
                cpa16(smem_u32(base + row * 40 + aseg * 8), &g_woh[(oh * 128 + row) * C_DIM + kc0 + aseg * 8]);
            }
            #pragma unroll
            for (int i = 0; i < 2; i++) {
                int row = brow + i * 16;
                size_t g = ((size_t)(b * 256 + kc0 + row)) * L_DIM + lt * 128 + bseg * 8;
                cpa16(smem_u32(base + 5120 + row * 136 + bseg * 8), &g_xth[g]);
            }
            CP_COMMIT();
        }

        __half* cur = dynsm + (it & 1) * PO_STAGE;
        __half* ah = cur;
        __half* bh_s = cur + 5120;

        uint32_t af[2][4];
        #pragma unroll
        for (int kc = 0; kc < 2; kc++)
            ldsm_x4(af[kc], smem_u32(&ah[(w * 16 + rr) * 40 + kc * 16 + chi]));

        #pragma unroll
        for (int nt = 0; nt < 16; nt += 2) {
            #pragma unroll
            for (int kc = 0; kc < 2; kc++) {
                uint32_t bh[4];
                ldsm_x4t(bh, smem_u32(&bh_s[(kc * 16 + rr) * 136 + nt * 8 + chi]));
                mma16816(acc[nt],     af[kc], bh);
                mma16816(acc[nt + 1], af[kc], bh + 2);
            }
        }
    }

    const int orow = oh * 128 + w * 16 + (lane >> 2);
    const float bb0 = bias_s[w * 16 + (lane >> 2)];
    const float bb1 = bias_s[w * 16 + (lane >> 2) + 8];
    #pragma unroll
    for (int nt = 0; nt < 16; nt++) {
        int lcol = lt * 128 + nt * 8 + (lane & 3) * 2;
        float2 y0, y1;
        y0.x = acc[nt][0] + bb0; y0.y = acc[nt][1] + bb0;
        y1.x = acc[nt][2] + bb1; y1.y = acc[nt][3] + bb1;
        *(float2*)&out[((size_t)(b * 256 + orow)) * L_DIM + lcol] = y0;
        *(float2*)&out[((size_t)(b * 256 + orow + 8)) * L_DIM + lcol] = y1;
    }
}

// ---------------------------------------------------------------------------
extern "C" void kernel_launch(void* const* d_in, const int* in_sizes, int n_in,
                              void* d_out, int out_size)
{
    const float* x  = (const float*)d_in[0];
    const float* wq = (const float*)d_in[1];
    const float* bq = (const float*)d_in[2];
    const float* wk = (const float*)d_in[3];
    const float* bk = (const float*)d_in[4];
    const float* wv = (const float*)d_in[5];
    const float* bv = (const float*)d_in[6];
    const float* wo = (const float*)d_in[7];
    const float* bo = (const float*)d_in[8];
    float* out = (float*)d_out;

    cudaFuncSetAttribute(proj_q_mma_kernel, cudaFuncAttributeMaxDynamicSharedMemorySize, PQ_BYTES);
    cudaFuncSetAttribute(proj_kv_mma_kernel, cudaFuncAttributeMaxDynamicSharedMemorySize, PJ_BYTES);
    cudaFuncSetAttribute(proj_o_mma_kernel, cudaFuncAttributeMaxDynamicSharedMemorySize, PO_BYTES);

    split_w_kernel<<<dim3(8, 8, 3), dim3(32, 8)>>>(wq, wk, wv);
    split_wo_kernel<<<128, 256>>>(wo);
    convert_x_kernel<<<dim3(32, 8, 16), dim3(32, 8)>>>(x);
    proj_kv_mma_kernel<<<dim3(16, 2, 16), 256, PJ_BYTES>>>(bk, bv);
    proj_q_mma_kernel<<<dim3(16, 1, 16), 256, PQ_BYTES>>>(bq);
    attn_mma_kernel<<<dim3(8, 8, 16), 256>>>();
    proj_o_mma_kernel<<<dim3(16, 1, 16), 256, PO_BYTES>>>(bo, out);
}

// round 17
// speedup vs baseline: 1.4046x; 1.0496x over previous
#include <cuda_runtime.h>
#include <cuda_fp16.h>
#include <cstdint>

#define C_DIM 256
#define L_DIM 1024
#define B_DIM 16
#define NH 8
#define DH 32
#define SCALE 0.17677669529663687f
#define LOG2E 1.4426950408889634f

// f16 hi/lo split buffers
__device__ __half g_qh[B_DIM * L_DIM * C_DIM];   // [b][l][c]
__device__ __half g_kth[B_DIM * L_DIM * C_DIM];  // k [b][l][c]
__device__ __half g_ktl[B_DIM * L_DIM * C_DIM];
__device__ __half g_vth[B_DIM * L_DIM * C_DIM];  // v [b][l][c] (hi only)
__device__ __half g_xth[B_DIM * L_DIM * C_DIM];  // x^T split; reused as att hi [b][c][l]
__device__ __half g_xtl[B_DIM * L_DIM * C_DIM];
__device__ __half g_wh[3 * C_DIM * C_DIM];       // W^T [sel][c][o]
__device__ __half g_wl[3 * C_DIM * C_DIM];
__device__ __half g_woh[C_DIM * C_DIM];          // Wo [o][c]

__device__ __forceinline__ float ex2f(float x) {
    float r; asm("ex2.approx.f32 %0, %1;" : "=f"(r) : "f"(x)); return r;
}
__device__ __forceinline__ uint32_t smem_u32(const void* p) {
    uint32_t a;
    asm("{ .reg .u64 t; cvta.to.shared.u64 t, %1; cvt.u32.u64 %0, t; }" : "=r"(a) : "l"(p));
    return a;
}
__device__ __forceinline__ uint32_t pack_h2(float lo, float hi) {
    uint32_t r; asm("cvt.rn.f16x2.f32 %0, %1, %2;" : "=r"(r) : "f"(hi), "f"(lo)); return r;
}
__device__ __forceinline__ void ldsm_x4(uint32_t* r, uint32_t a) {
    asm volatile("ldmatrix.sync.aligned.m8n8.x4.shared.b16 {%0,%1,%2,%3}, [%4];"
        : "=r"(r[0]), "=r"(r[1]), "=r"(r[2]), "=r"(r[3]) : "r"(a));
}
__device__ __forceinline__ void ldsm_x4t(uint32_t* r, uint32_t a) {
    asm volatile("ldmatrix.sync.aligned.m8n8.x4.trans.shared.b16 {%0,%1,%2,%3}, [%4];"
        : "=r"(r[0]), "=r"(r[1]), "=r"(r[2]), "=r"(r[3]) : "r"(a));
}
__device__ __forceinline__ void mma16816(float* d, const uint32_t* a, const uint32_t* b) {
    asm volatile("mma.sync.aligned.m16n8k16.row.col.f32.f16.f16.f32 "
        "{%0,%1,%2,%3}, {%4,%5,%6,%7}, {%8,%9}, {%0,%1,%2,%3};"
        : "+f"(d[0]), "+f"(d[1]), "+f"(d[2]), "+f"(d[3])
        : "r"(a[0]), "r"(a[1]), "r"(a[2]), "r"(a[3]), "r"(b[0]), "r"(b[1]));
}
__device__ __forceinline__ float shflx(float v, int m) {
    return __shfl_xor_sync(0xffffffffu, v, m);
}
__device__ __forceinline__ void cpa16(uint32_t s, const void* g) {
    asm volatile("cp.async.cg.shared.global [%0], [%1], 16;" :: "r"(s), "l"(g));
}
#define CP_COMMIT() asm volatile("cp.async.commit_group;" ::: "memory")
#define CP_WAIT0()  asm volatile("cp.async.wait_group 0;" ::: "memory")

// ------------------- prep kernels -------------------
__global__ void __launch_bounds__(256)
split_w_kernel(const float* __restrict__ wq, const float* __restrict__ wk, const float* __restrict__ wv)
{
    __shared__ float t[32][33];
    const int sel = blockIdx.z;
    const float* W = (sel == 0) ? wq : (sel == 1) ? wk : wv;
    __half* dh = g_wh + sel * C_DIM * C_DIM;
    __half* dl = g_wl + sel * C_DIM * C_DIM;
    const int o0 = blockIdx.x * 32, c0 = blockIdx.y * 32;
    const int tx = threadIdx.x, ty = threadIdx.y;
    #pragma unroll
    for (int i = 0; i < 4; i++)
        t[ty + 8 * i][tx] = W[(o0 + ty + 8 * i) * C_DIM + c0 + tx];
    __syncthreads();
    #pragma unroll
    for (int i = 0; i < 4; i++) {
        float v = t[tx][ty + 8 * i];
        __half h = __float2half_rn(v);
        int o = (c0 + ty + 8 * i) * C_DIM + o0 + tx;
        dh[o] = h;
        dl[o] = __float2half_rn(v - __half2float(h));
    }
}

__global__ void __launch_bounds__(256)
split_wo_kernel(const float* __restrict__ wo)
{
    int i = blockIdx.x * 256 + threadIdx.x;
    const float2 v = ((const float2*)wo)[i];
    ((__half2*)g_woh)[i] = __floats2half2_rn(v.x, v.y);
}

__global__ void __launch_bounds__(256)
convert_x_kernel(const float* __restrict__ x)
{
    __shared__ float t[32][33];
    const int b = blockIdx.z;
    const float* src = x + (size_t)b * C_DIM * L_DIM;
    __half* dh = g_xth + (size_t)b * L_DIM * C_DIM;
    __half* dl = g_xtl + (size_t)b * L_DIM * C_DIM;
    const int l0 = blockIdx.x * 32, c0 = blockIdx.y * 32;
    const int tx = threadIdx.x, ty = threadIdx.y;
    #pragma unroll
    for (int i = 0; i < 4; i++)
        t[ty + 8 * i][tx] = src[(size_t)(c0 + ty + 8 * i) * L_DIM + l0 + tx];
    __syncthreads();
    #pragma unroll
    for (int i = 0; i < 4; i++) {
        float v = t[tx][ty + 8 * i];
        __half h = __float2half_rn(v);
        size_t o = (size_t)(l0 + ty + 8 * i) * C_DIM + c0 + tx;
        dh[o] = h;
        dl[o] = __float2half_rn(v - __half2float(h));
    }
}

// ------------------- projection constants -------------------
#define PJ_STAGE 18944
#define PJ_BYTES (2 * PJ_STAGE * 2)
#define PQ_STAGE 14592
#define PQ_BYTES (2 * PQ_STAGE * 2)
#define PO_STAGE 9472
#define PO_BYTES (2 * PO_STAGE * 2)

// ------------------- q/v projection: 2-term (W * (xh+xl)), hi-only output -------------------
__global__ void __launch_bounds__(256, 2)
proj_qv_mma_kernel(const float* __restrict__ bq, const float* __restrict__ bv)
{
    extern __shared__ __half dynsm[];
    __shared__ float bias_s[128];

    const int tid = threadIdx.x, lane = tid & 31, w = tid >> 5;
    const int lt = blockIdx.x >> 1, oh = blockIdx.x & 1;
    const int isv = blockIdx.y;            // 0 = q, 1 = v
    const int b = blockIdx.z;

    const __half* xh = g_xth + (size_t)b * L_DIM * C_DIM;
    const __half* xl = g_xtl + (size_t)b * L_DIM * C_DIM;
    const __half* wh = g_wh + (isv ? 2 : 0) * C_DIM * C_DIM;
    const float* bias = isv ? bv : bq;
    __half* Yh = isv ? g_vth : g_qh;
    const float sc = isv ? 1.0f : (SCALE * LOG2E);

    if (tid < 128) bias_s[tid] = bias[oh * 128 + tid];

    const int arow = tid >> 2, aseg = tid & 3;
    const int brow = tid >> 4, bseg = tid & 15;

    {
        __half* base = dynsm;
        #pragma unroll
        for (int i = 0; i < 2; i++) {
            int row = arow + i * 64;
            size_t g = (size_t)(lt * 128 + row) * C_DIM + aseg * 8;
            cpa16(smem_u32(base + row * 40 + aseg * 8), &xh[g]);
            cpa16(smem_u32(base + 5120 + row * 40 + aseg * 8), &xl[g]);
        }
        #pragma unroll
        for (int i = 0; i < 2; i++) {
            int row = brow + i * 16;
            cpa16(smem_u32(base + 10240 + row * 136 + bseg * 8), &wh[row * C_DIM + oh * 128 + bseg * 8]);
        }
        CP_COMMIT();
    }

    float acc[16][4] = {};
    const int rr = lane & 15;
    const int chi = (lane & 16) ? 8 : 0;

    for (int it = 0; it < 8; it++) {
        CP_WAIT0();
        __syncthreads();

        if (it < 7) {
            __half* base = dynsm + ((it + 1) & 1) * PQ_STAGE;
            int kc0 = (it + 1) * 32;
            #pragma unroll
            for (int i = 0; i < 2; i++) {
                int row = arow + i * 64;
                size_t g = (size_t)(lt * 128 + row) * C_DIM + kc0 + aseg * 8;
                cpa16(smem_u32(base + row * 40 + aseg * 8), &xh[g]);
                cpa16(smem_u32(base + 5120 + row * 40 + aseg * 8), &xl[g]);
            }
            #pragma unroll
            for (int i = 0; i < 2; i++) {
                int row = brow + i * 16;
                cpa16(smem_u32(base + 10240 + row * 136 + bseg * 8), &wh[(kc0 + row) * C_DIM + oh * 128 + bseg * 8]);
            }
            CP_COMMIT();
        }

        __half* cur = dynsm + (it & 1) * PQ_STAGE;
        __half* ah = cur;
        __half* al = cur + 5120;
        __half* bh_s = cur + 10240;

        uint32_t af[2][2][4];
        #pragma unroll
        for (int kc = 0; kc < 2; kc++) {
            ldsm_x4(af[0][kc], smem_u32(&ah[(w * 16 + rr) * 40 + kc * 16 + chi]));
            ldsm_x4(af[1][kc], smem_u32(&al[(w * 16 + rr) * 40 + kc * 16 + chi]));
        }

        #pragma unroll
        for (int nt = 0; nt < 16; nt += 2) {
            #pragma unroll
            for (int kc = 0; kc < 2; kc++) {
                uint32_t bh[4];
                ldsm_x4t(bh, smem_u32(&bh_s[(kc * 16 + rr) * 136 + nt * 8 + chi]));
                mma16816(acc[nt],     af[0][kc], bh);
                mma16816(acc[nt + 1], af[0][kc], bh + 2);
                mma16816(acc[nt],     af[1][kc], bh);
                mma16816(acc[nt + 1], af[1][kc], bh + 2);
            }
        }
    }

    const int r0 = lt * 128 + w * 16 + (lane >> 2);
    #pragma unroll
    for (int nt = 0; nt < 16; nt++) {
        int c0 = nt * 8 + (lane & 3) * 2;
        float b0 = bias_s[c0], b1 = bias_s[c0 + 1];
        float v0 = (acc[nt][0] + b0) * sc, v1 = (acc[nt][1] + b1) * sc;
        float v2 = (acc[nt][2] + b0) * sc, v3 = (acc[nt][3] + b1) * sc;
        size_t o0 = (size_t)(b * 1024 + r0) * C_DIM + oh * 128 + c0;
        size_t o1 = (size_t)(b * 1024 + r0 + 8) * C_DIM + oh * 128 + c0;
        *(__half2*)&Yh[o0] = __floats2half2_rn(v0, v1);
        *(__half2*)&Yh[o1] = __floats2half2_rn(v2, v3);
    }
}

// ------------------- k projection: 3-term, hi+lo output -------------------
__global__ void __launch_bounds__(256, 2)
proj_k_mma_kernel(const float* __restrict__ bk)
{
    extern __shared__ __half dynsm[];
    __shared__ float bias_s[128];

    const int tid = threadIdx.x, lane = tid & 31, w = tid >> 5;
    const int lt = blockIdx.x >> 1, oh = blockIdx.x & 1;
    const int b = blockIdx.z;

    const __half* xh = g_xth + (size_t)b * L_DIM * C_DIM;
    const __half* xl = g_xtl + (size_t)b * L_DIM * C_DIM;
    const __half* wh = g_wh + 1 * C_DIM * C_DIM;
    const __half* wl = g_wl + 1 * C_DIM * C_DIM;

    if (tid < 128) bias_s[tid] = bk[oh * 128 + tid];

    const int arow = tid >> 2, aseg = tid & 3;
    const int brow = tid >> 4, bseg = tid & 15;

    {
        __half* base = dynsm;
        #pragma unroll
        for (int i = 0; i < 2; i++) {
            int row = arow + i * 64;
            size_t g = (size_t)(lt * 128 + row) * C_DIM + aseg * 8;
            cpa16(smem_u32(base + row * 40 + aseg * 8), &xh[g]);
            cpa16(smem_u32(base + 5120 + row * 40 + aseg * 8), &xl[g]);
        }
        #pragma unroll
        for (int i = 0; i < 2; i++) {
            int row = brow + i * 16;
            int g = row * C_DIM + oh * 128 + bseg * 8;
            cpa16(smem_u32(base + 10240 + row * 136 + bseg * 8), &wh[g]);
            cpa16(smem_u32(base + 14592 + row * 136 + bseg * 8), &wl[g]);
        }
        CP_COMMIT();
    }

    float acc[16][4] = {};
    const int rr = lane & 15;
    const int chi = (lane & 16) ? 8 : 0;

    for (int it = 0; it < 8; it++) {
        CP_WAIT0();
        __syncthreads();

        if (it < 7) {
            __half* base = dynsm + ((it + 1) & 1) * PJ_STAGE;
            int kc0 = (it + 1) * 32;
            #pragma unroll
            for (int i = 0; i < 2; i++) {
                int row = arow + i * 64;
                size_t g = (size_t)(lt * 128 + row) * C_DIM + kc0 + aseg * 8;
                cpa16(smem_u32(base + row * 40 + aseg * 8), &xh[g]);
                cpa16(smem_u32(base + 5120 + row * 40 + aseg * 8), &xl[g]);
            }
            #pragma unroll
            for (int i = 0; i < 2; i++) {
                int row = brow + i * 16;
                int g = (kc0 + row) * C_DIM + oh * 128 + bseg * 8;
                cpa16(smem_u32(base + 10240 + row * 136 + bseg * 8), &wh[g]);
                cpa16(smem_u32(base + 14592 + row * 136 + bseg * 8), &wl[g]);
            }
            CP_COMMIT();
        }

        __half* cur = dynsm + (it & 1) * PJ_STAGE;
        __half* ah = cur;
        __half* al = cur + 5120;
        __half* bh_s = cur + 10240;
        __half* bl_s = cur + 14592;

        uint32_t af[2][2][4];
        #pragma unroll
        for (int kc = 0; kc < 2; kc++) {
            ldsm_x4(af[0][kc], smem_u32(&ah[(w * 16 + rr) * 40 + kc * 16 + chi]));
            ldsm_x4(af[1][kc], smem_u32(&al[(w * 16 + rr) * 40 + kc * 16 + chi]));
        }

        #pragma unroll
        for (int nt = 0; nt < 16; nt += 2) {
            #pragma unroll
            for (int kc = 0; kc < 2; kc++) {
                uint32_t bh[4], bl[4];
                ldsm_x4t(bh, smem_u32(&bh_s[(kc * 16 + rr) * 136 + nt * 8 + chi]));
                ldsm_x4t(bl, smem_u32(&bl_s[(kc * 16 + rr) * 136 + nt * 8 + chi]));
                mma16816(acc[nt],     af[0][kc], bh);
                mma16816(acc[nt + 1], af[0][kc], bh + 2);
                mma16816(acc[nt],     af[0][kc], bl);
                mma16816(acc[nt + 1], af[0][kc], bl + 2);
                mma16816(acc[nt],     af[1][kc], bh);
                mma16816(acc[nt + 1], af[1][kc], bh + 2);
            }
        }
    }

    const int r0 = lt * 128 + w * 16 + (lane >> 2);
    #pragma unroll
    for (int nt = 0; nt < 16; nt++) {
        int c0 = nt * 8 + (lane & 3) * 2;
        float b0 = bias_s[c0], b1 = bias_s[c0 + 1];
        float v0 = acc[nt][0] + b0, v1 = acc[nt][1] + b1;
        float v2 = acc[nt][2] + b0, v3 = acc[nt][3] + b1;
        __half2 h0 = __floats2half2_rn(v0, v1);
        __half2 h1 = __floats2half2_rn(v2, v3);
        float2 f0 = __half22float2(h0);
        float2 f1 = __half22float2(h1);
        size_t o0 = (size_t)(b * 1024 + r0) * C_DIM + oh * 128 + c0;
        size_t o1 = (size_t)(b * 1024 + r0 + 8) * C_DIM + oh * 128 + c0;
        *(__half2*)&g_kth[o0] = h0;
        *(__half2*)&g_kth[o1] = h1;
        *(__half2*)&g_ktl[o0] = __floats2half2_rn(v0 - f0.x, v1 - f0.y);
        *(__half2*)&g_ktl[o1] = __floats2half2_rn(v2 - f1.x, v3 - f1.y);
    }
}

// ------------------- flash attention (byte-identical to R16 win) -------------------
__global__ void __launch_bounds__(256, 2)
attn_mma_kernel()
{
    __shared__ __align__(16) __half pool[15360];

    const int tid = threadIdx.x, lane = tid & 31, w = tid >> 5;
    const int qt = blockIdx.x, n = blockIdx.y, b = blockIdx.z;
    const int rr = lane & 15;
    const int hoff = (lane & 16) ? 8 : 0;
    const int knr = (lane & 7) + ((lane >> 4) << 3);
    const int knc = ((lane >> 3) & 1) * 8;
    const int kvrow = tid >> 2, kvseg = tid & 3;

    {
        __half* base = pool + 7680;
        size_t g = ((size_t)(b * 1024 + kvrow)) * C_DIM + n * 32 + kvseg * 8;
        uint32_t s = smem_u32(base + kvrow * 40 + kvseg * 8);
        cpa16(s, &g_kth[g]);
        cpa16(s + 2560 * 2, &g_ktl[g]);
        cpa16(s + 5120 * 2, &g_vth[g]);
        CP_COMMIT();
    }

    for (int u = tid; u < 512; u += 256) {
        int row = u >> 2, seg = u & 3;
        size_t g = ((size_t)(b * 1024 + qt * 128 + row)) * C_DIM + n * 32 + seg * 8;
        *(uint4*)&pool[row * 40 + seg * 8] = *(const uint4*)&g_qh[g];
    }
    __syncthreads();

    uint32_t qf[2][4];
    #pragma unroll
    for (int kc = 0; kc < 2; kc++)
        ldsm_x4(qf[kc], smem_u32(&pool[(w * 16 + rr) * 40 + kc * 16 + hoff]));
    __syncthreads();

    float oacc[4][4] = {};
    float l0 = 0.0f, l1 = 0.0f;

    for (int t = 0; t < 16; t++) {
        CP_WAIT0();
        __syncthreads();

        if (t < 15) {
            __half* base = pool + (((t + 1) & 1) ? 0 : 7680);
            size_t g = ((size_t)(b * 1024 + (t + 1) * 64 + kvrow)) * C_DIM + n * 32 + kvseg * 8;
            uint32_t s = smem_u32(base + kvrow * 40 + kvseg * 8);
            cpa16(s, &g_kth[g]);
            cpa16(s + 2560 * 2, &g_ktl[g]);
            cpa16(s + 5120 * 2, &g_vth[g]);
            CP_COMMIT();
        }

        __half* cur = pool + ((t & 1) ? 0 : 7680);
        __half* ksh0 = cur;
        __half* ksh1 = cur + 2560;
        __half* vsh0 = cur + 5120;

        float sacc[8][4];
        #pragma unroll
        for (int ntp = 0; ntp < 4; ntp++) {
            float* s0 = sacc[2 * ntp];
            float* s1 = sacc[2 * ntp + 1];
            s0[0] = s0[1] = s0[2] = s0[3] = 0.0f;
            s1[0] = s1[1] = s1[2] = s1[3] = 0.0f;
            #pragma unroll
            for (int kc = 0; kc < 2; kc++) {
                uint32_t off = (ntp * 16 + knr) * 40 + kc * 16 + knc;
                uint32_t kbh[4], kbl[4];
                ldsm_x4(kbh, smem_u32(&ksh0[off]));
                ldsm_x4(kbl, smem_u32(&ksh1[off]));
                mma16816(s0, qf[kc], kbh);
                mma16816(s1, qf[kc], kbh + 2);
                mma16816(s0, qf[kc], kbl);
                mma16816(s1, qf[kc], kbl + 2);
            }
        }

        float rs0 = 0.0f, rs1 = 0.0f;
        #pragma unroll
        for (int nt = 0; nt < 8; nt++) {
            sacc[nt][0] = ex2f(sacc[nt][0]);
            sacc[nt][1] = ex2f(sacc[nt][1]);
            sacc[nt][2] = ex2f(sacc[nt][2]);
            sacc[nt][3] = ex2f(sacc[nt][3]);
            rs0 += sacc[nt][0] + sacc[nt][1];
            rs1 += sacc[nt][2] + sacc[nt][3];
        }
        rs0 += shflx(rs0, 1); rs0 += shflx(rs0, 2);
        rs1 += shflx(rs1, 1); rs1 += shflx(rs1, 2);
        l0 += rs0; l1 += rs1;

        uint32_t pfh[4][4];
        #pragma unroll
        for (int kc = 0; kc < 4; kc++) {
            const float* s0 = sacc[2 * kc];
            const float* s1 = sacc[2 * kc + 1];
            pfh[kc][0] = pack_h2(s0[0], s0[1]);
            pfh[kc][1] = pack_h2(s0[2], s0[3]);
            pfh[kc][2] = pack_h2(s1[0], s1[1]);
            pfh[kc][3] = pack_h2(s1[2], s1[3]);
        }

        #pragma unroll
        for (int kc = 0; kc < 4; kc++) {
            #pragma unroll
            for (int np = 0; np < 2; np++) {
                uint32_t vbh[4];
                uint32_t off = (kc * 16 + rr) * 40 + np * 16 + hoff;
                ldsm_x4t(vbh, smem_u32(&vsh0[off]));
                mma16816(oacc[2 * np],     pfh[kc], vbh);
                mma16816(oacc[2 * np + 1], pfh[kc], vbh + 2);
            }
        }
    }

    float i0 = 1.0f / l0, i1 = 1.0f / l1;
    int q0 = qt * 128 + w * 16 + (lane >> 2);
    #pragma unroll
    for (int nt = 0; nt < 4; nt++) {
        int c = n * 32 + nt * 8 + (lane & 3) * 2;
        size_t b0 = ((size_t)(b * 256 + c)) * L_DIM + q0;
        size_t b1 = b0 + L_DIM;
        g_xth[b0] = __float2half_rn(oacc[nt][0] * i0);
        g_xth[b1] = __float2half_rn(oacc[nt][1] * i0);
        g_xth[b0 + 8] = __float2half_rn(oacc[nt][2] * i1);
        g_xth[b1 + 8] = __float2half_rn(oacc[nt][3] * i1);
    }
}

// ------------------- mma output projection (byte-identical to R16 win) -------------------
__global__ void __launch_bounds__(256)
proj_o_mma_kernel(const float* __restrict__ bo, float* __restrict__ out)
{
    extern __shared__ __half dynsm[];
    __shared__ float bias_s[128];

    const int tid = threadIdx.x, lane = tid & 31, w = tid >> 5;
    const int lt = blockIdx.x >> 1, oh = blockIdx.x & 1;
    const int b = blockIdx.z;

    if (tid < 128) bias_s[tid] = bo[oh * 128 + tid];

    const int arow = tid >> 2, aseg = tid & 3;
    const int brow = tid >> 4, bseg = tid & 15;

    {
        __half* base = dynsm;
        #pragma unroll
        for (int i = 0; i < 2; i++) {
            int row = arow + i * 64;
            cpa16(smem_u32(base + row * 40 + aseg * 8), &g_woh[(oh * 128 + row) * C_DIM + aseg * 8]);
        }
        #pragma unroll
        for (int i = 0; i < 2; i++) {
            int row = brow + i * 16;
            size_t g = ((size_t)(b * 256 + row)) * L_DIM + lt * 128 + bseg * 8;
            cpa16(smem_u32(base + 5120 + row * 136 + bseg * 8), &g_xth[g]);
        }
        CP_COMMIT();
    }

    float acc[16][4] = {};
    const int rr = lane & 15;
    const int chi = (lane & 16) ? 8 : 0;

    for (int it = 0; it < 8; it++) {
        CP_WAIT0();
        __syncthreads();

        if (it < 7) {
            __half* base = dynsm + ((it + 1) & 1) * PO_STAGE;
            int kc0 = (it + 1) * 32;
            #pragma unroll
            for (int i = 0; i < 2; i++) {
                int row = arow + i * 64;
                cpa16(smem_u32(base + row * 40 + aseg * 8), &g_woh[(oh * 128 + row) * C_DIM + kc0 + aseg * 8]);
            }
            #pragma unroll
            for (int i = 0; i < 2; i++) {
                int row = brow + i * 16;
                size_t g = ((size_t)(b * 256 + kc0 + row)) * L_DIM + lt * 128 + bseg * 8;
                cpa16(smem_u32(base + 5120 + row * 136 + bseg * 8), &g_xth[g]);
            }
            CP_COMMIT();
        }

        __half* cur = dynsm + (it & 1) * PO_STAGE;
        __half* ah = cur;
        __half* bh_s = cur + 5120;

        uint32_t af[2][4];
        #pragma unroll
        for (int kc = 0; kc < 2; kc++)
            ldsm_x4(af[kc], smem_u32(&ah[(w * 16 + rr) * 40 + kc * 16 + chi]));

        #pragma unroll
        for (int nt = 0; nt < 16; nt += 2) {
            #pragma unroll
            for (int kc = 0; kc < 2; kc++) {
                uint32_t bh[4];
                ldsm_x4t(bh, smem_u32(&bh_s[(kc * 16 + rr) * 136 + nt * 8 + chi]));
                mma16816(acc[nt],     af[kc], bh);
                mma16816(acc[nt + 1], af[kc], bh + 2);
            }
        }
    }

    const int orow = oh * 128 + w * 16 + (lane >> 2);
    const float bb0 = bias_s[w * 16 + (lane >> 2)];
    const float bb1 = bias_s[w * 16 + (lane >> 2) + 8];
    #pragma unroll
    for (int nt = 0; nt < 16; nt++) {
        int lcol = lt * 128 + nt * 8 + (lane & 3) * 2;
        float2 y0, y1;
        y0.x = acc[nt][0] + bb0; y0.y = acc[nt][1] + bb0;
        y1.x = acc[nt][2] + bb1; y1.y = acc[nt][3] + bb1;
        *(float2*)&out[((size_t)(b * 256 + orow)) * L_DIM + lcol] = y0;
        *(float2*)&out[((size_t)(b * 256 + orow + 8)) * L_DIM + lcol] = y1;
    }
}

// ---------------------------------------------------------------------------
extern "C" void kernel_launch(void* const* d_in, const int* in_sizes, int n_in,
                              void* d_out, int out_size)
{
    const float* x  = (const float*)d_in[0];
    const float* wq = (const float*)d_in[1];
    const float* bq = (const float*)d_in[2];
    const float* wk = (const float*)d_in[3];
    const float* bk = (const float*)d_in[4];
    const float* wv = (const float*)d_in[5];
    const float* bv = (const float*)d_in[6];
    const float* wo = (const float*)d_in[7];
    const float* bo = (const float*)d_in[8];
    float* out = (float*)d_out;

    cudaFuncSetAttribute(proj_qv_mma_kernel, cudaFuncAttributeMaxDynamicSharedMemorySize, PQ_BYTES);
    cudaFuncSetAttribute(proj_k_mma_kernel, cudaFuncAttributeMaxDynamicSharedMemorySize, PJ_BYTES);
    cudaFuncSetAttribute(proj_o_mma_kernel, cudaFuncAttributeMaxDynamicSharedMemorySize, PO_BYTES);

    split_w_kernel<<<dim3(8, 8, 3), dim3(32, 8)>>>(wq, wk, wv);
    split_wo_kernel<<<128, 256>>>(wo);
    convert_x_kernel<<<dim3(32, 8, 16), dim3(32, 8)>>>(x);
    proj_k_mma_kernel<<<dim3(16, 1, 16), 256, PJ_BYTES>>>(bk);
    proj_qv_mma_kernel<<<dim3(16, 2, 16), 256, PQ_BYTES>>>(bq, bv);
    attn_mma_kernel<<<dim3(8, 8, 16), 256>>>();
    proj_o_mma_kernel<<<dim3(16, 1, 16), 256, PO_BYTES>>>(bo, out);
}